// round 6
// baseline (speedup 1.0000x reference)
#include <cuda_runtime.h>
#include <cuda_bf16.h>
#include <cstdint>
#include <cfloat>

// ---------------------------------------------------------------------------
// Problem constants
// ---------------------------------------------------------------------------
#define M_TOTAL 16384
#define K_CODES 8192
#define DIM     512             // tf32 GEMM K = 512 (single term!)
#define MT      64              // rows per CTA (2 CTAs/SM)
#define BN      128             // codes per chunk
#define NCHUNK  (K_CODES / BN)  // 64
#define BK      64              // fp32 K per pipeline step (256 B/row)
#define KSTEPS  (DIM / BK)      // 8
#define NTHR    256

// ---------------------------------------------------------------------------
// Scratch (static device arrays: allocation-free rule)
// ---------------------------------------------------------------------------
__device__ float g_At[(size_t)M_TOTAL * DIM];   // tf32-rounded x   (32 MB)
__device__ float g_Bt[(size_t)K_CODES * DIM];   // tf32-rounded emb (16 MB)
__device__ float g_e2[K_CODES];
__device__ int4  g_top[M_TOTAL];                // top-4 candidate indices

// ---------------------------------------------------------------------------
// Baseline-PTX helpers (no "a"-suffix arch features)
// ---------------------------------------------------------------------------
__device__ __forceinline__ uint32_t smem_u32(const void* p) {
    uint32_t a;
    asm("{ .reg .u64 t; cvta.to.shared.u64 t, %1; cvt.u32.u64 %0, t; }"
        : "=r"(a) : "l"(p));
    return a;
}

__device__ __forceinline__ void cp_async16(uint32_t dst, const void* src) {
    uint64_t g;
    asm("cvta.to.global.u64 %0, %1;" : "=l"(g) : "l"(src));
    asm volatile("cp.async.cg.shared.global [%0], [%1], 16;"
                 :: "r"(dst), "l"(g) : "memory");
}
#define CP_COMMIT() asm volatile("cp.async.commit_group;" ::: "memory")

__device__ __forceinline__ void ldmatrix_x4(uint32_t& r0, uint32_t& r1,
                                            uint32_t& r2, uint32_t& r3,
                                            uint32_t addr) {
    asm volatile("ldmatrix.sync.aligned.m8n8.x4.shared.b16 {%0,%1,%2,%3}, [%4];"
                 : "=r"(r0), "=r"(r1), "=r"(r2), "=r"(r3) : "r"(addr));
}

// m16n8k8 tf32 MMA (sm_80 baseline PTX)
__device__ __forceinline__ void mma_tf32(float& d0, float& d1, float& d2, float& d3,
                                         uint32_t a0, uint32_t a1, uint32_t a2, uint32_t a3,
                                         uint32_t b0, uint32_t b1) {
    asm volatile(
        "mma.sync.aligned.m16n8k8.row.col.f32.tf32.tf32.f32 "
        "{%0,%1,%2,%3}, {%4,%5,%6,%7}, {%8,%9}, {%0,%1,%2,%3};"
        : "+f"(d0), "+f"(d1), "+f"(d2), "+f"(d3)
        : "r"(a0), "r"(a1), "r"(a2), "r"(a3), "r"(b0), "r"(b1));
}

// 256 B rows: 16 x 16B chunks; XOR-swizzle low 3 bits within each 128B half.
__device__ __forceinline__ uint32_t swz16(int c, int row) {
    return (uint32_t)((((c ^ (row & 7)) & 7) | (c & 8)) * 16);
}

// ---------------------------------------------------------------------------
// SMEM layout (dynamic): ~106 KB per CTA -> 2 CTAs/SM
// ---------------------------------------------------------------------------
#define SM_E2      0                         // 128 floats
#define SM_MBS     1024                      // 64 rows x 4 warps x float4 = 4 KB
#define SM_MBI     5120                      // 64 rows x 4 warps x int4   = 4 KB
#define SM_A       10240                     // 2 stages x 16 KB (64 x 256 B)
#define A_STAGE    16384
#define SM_B       (SM_A + 2 * A_STAGE)      // 43008, 2 stages x 32 KB (128 x 256 B)
#define B_STAGE    32768
#define SMEM_TOTAL (SM_B + 2 * B_STAGE)      // 108544  (x2 = 217 KB/SM)

// ---------------------------------------------------------------------------
// Kernel: e2[k] = ||emb_k||^2 (exact fp32, from ORIGINAL emb)
// ---------------------------------------------------------------------------
__global__ void e2_kernel(const float* __restrict__ emb) {
    int row  = blockIdx.x * 8 + (threadIdx.x >> 5);
    int lane = threadIdx.x & 31;
    const float4* p = reinterpret_cast<const float4*>(emb + (size_t)row * DIM);
    float s = 0.f;
#pragma unroll
    for (int i = 0; i < 4; ++i) {
        float4 v = p[lane + i * 32];
        s += v.x * v.x + v.y * v.y + v.z * v.z + v.w * v.w;
    }
#pragma unroll
    for (int o = 16; o; o >>= 1) s += __shfl_xor_sync(0xffffffffu, s, o);
    if (lane == 0) g_e2[row] = s;
}

// ---------------------------------------------------------------------------
// Kernel: tf32-round (RNA) copies. dst[i] = cvt.rna.tf32(src[i])
// ---------------------------------------------------------------------------
__device__ __forceinline__ float to_tf32(float v) {
    uint32_t o;
    asm("cvt.rna.tf32.f32 %0, %1;" : "=r"(o) : "f"(v));
    return __uint_as_float(o);
}

__global__ void round_x_kernel(const float* __restrict__ src) {
    int i = blockIdx.x * 256 + threadIdx.x;           // float4 index
    float4 v = reinterpret_cast<const float4*>(src)[i];
    float4 o = make_float4(to_tf32(v.x), to_tf32(v.y), to_tf32(v.z), to_tf32(v.w));
    reinterpret_cast<float4*>(g_At)[i] = o;
}

__global__ void round_e_kernel(const float* __restrict__ src) {
    int i = blockIdx.x * 256 + threadIdx.x;
    float4 v = reinterpret_cast<const float4*>(src)[i];
    float4 o = make_float4(to_tf32(v.x), to_tf32(v.y), to_tf32(v.z), to_tf32(v.w));
    reinterpret_cast<float4*>(g_Bt)[i] = o;
}

// ---------------------------------------------------------------------------
// Top-4 insert (descending score, ascending index on ties)
// ---------------------------------------------------------------------------
#define BET(s, i, b, j) ((s) > (b) || ((s) == (b) && (i) < (j)))

__device__ __forceinline__ void top4_upd(float* b, int* ix, float s, int idx) {
    if (!BET(s, idx, b[3], ix[3])) return;            // common fast path
    if (BET(s, idx, b[0], ix[0])) {
        b[3]=b[2]; ix[3]=ix[2]; b[2]=b[1]; ix[2]=ix[1];
        b[1]=b[0]; ix[1]=ix[0]; b[0]=s;  ix[0]=idx;
    } else if (BET(s, idx, b[1], ix[1])) {
        b[3]=b[2]; ix[3]=ix[2]; b[2]=b[1]; ix[2]=ix[1];
        b[1]=s;  ix[1]=idx;
    } else if (BET(s, idx, b[2], ix[2])) {
        b[3]=b[2]; ix[3]=ix[2]; b[2]=s;  ix[2]=idx;
    } else {
        b[3]=s;  ix[3]=idx;
    }
}

// ---------------------------------------------------------------------------
// Main kernel: TF32 HMMA GEMM + fused per-row top-4
// ---------------------------------------------------------------------------
__device__ __forceinline__ void fill_stage(uint32_t sb, int stage, int step,
                                           int m0, int n0, int tid) {
    const int gk = step * BK;                         // float offset
    uint32_t ab = sb + SM_A + stage * A_STAGE;
#pragma unroll
    for (int j = 0; j < 4; ++j) {                     // A: 64 rows x 16 chunks
        int id = tid + j * 256;
        int row = id >> 4, c = id & 15;
        const void* src = g_At + (size_t)(m0 + row) * DIM + gk + c * 4;
        cp_async16(ab + row * 256 + swz16(c, row), src);
    }
    uint32_t bb = sb + SM_B + stage * B_STAGE;
#pragma unroll
    for (int j = 0; j < 8; ++j) {                     // B: 128 rows x 16 chunks
        int id = tid + j * 256;
        int row = id >> 4, c = id & 15;
        const void* src = g_Bt + (size_t)(n0 + row) * DIM + gk + c * 4;
        cp_async16(bb + row * 256 + swz16(c, row), src);
    }
    CP_COMMIT();
}

__global__ void __launch_bounds__(NTHR, 2)
vq_main_kernel() {
    extern __shared__ char smem[];
    uint32_t sb = smem_u32(smem);
    float*  e2s   = reinterpret_cast<float*>(smem + SM_E2);
    float4* mbufS = reinterpret_cast<float4*>(smem + SM_MBS);
    int4*   mbufI = reinterpret_cast<int4*>(smem + SM_MBI);

    const int tid  = threadIdx.x;
    const int lane = tid & 31;
    const int wid  = tid >> 5;
    const int wm   = wid >> 2;     // 0..1 (m half: 32 rows)
    const int wn   = wid & 3;      // 0..3 (n quarter: 32 cols)
    const int m0   = blockIdx.x * MT;

    float rb[4] = {-FLT_MAX, -FLT_MAX, -FLT_MAX, -FLT_MAX};
    int   ri[4] = {0x7fffffff, 0x7fffffff, 0x7fffffff, 0x7fffffff};

    // Prologue: stage 0 of chunk 0.
    fill_stage(sb, 0, 0, m0, 0, tid);

#pragma unroll 1
    for (int ch = 0; ch < NCHUNK; ++ch) {
        const int n0 = ch * BN;
        if (tid < BN) e2s[tid] = g_e2[n0 + tid];

        float acc[2][4][4];
#pragma unroll
        for (int a = 0; a < 2; ++a)
#pragma unroll
            for (int b = 0; b < 4; ++b)
#pragma unroll
                for (int c = 0; c < 4; ++c) acc[a][b][c] = 0.f;

#pragma unroll 1
        for (int st = 0; st < KSTEPS; ++st) {
            asm volatile("cp.async.wait_group 0;" ::: "memory");
            __syncthreads();
            if (st + 1 < KSTEPS)
                fill_stage(sb, (st + 1) & 1, st + 1, m0, n0, tid);
            else if (ch + 1 < NCHUNK)
                fill_stage(sb, 0, 0, m0, n0 + BN, tid);   // next chunk, stage 0

            const uint32_t ab = sb + SM_A + (st & 1) * A_STAGE;
            const uint32_t bb = sb + SM_B + (st & 1) * B_STAGE;

#pragma unroll
            for (int sub = 0; sub < 8; ++sub) {           // 8 x k8 per BK=64
                // ---- B fragments: 4 n-frags, 2 regs each = 2 ldmatrix.x4 ----
                // x4 tile order: (n 0-7, c even), (n 0-7, c odd),
                //                (n 8-15, c even), (n 8-15, c odd)
                uint32_t bfr[4][2];
#pragma unroll
                for (int p = 0; p < 2; ++p) {
                    int row = wn * 32 + p * 16 + ((lane >> 4) & 1) * 8 + (lane & 7);
                    int c   = sub * 2 + ((lane >> 3) & 1);
                    uint32_t addr = bb + row * 256 + swz16(c, row);
                    ldmatrix_x4(bfr[p*2][0], bfr[p*2][1],
                                bfr[p*2+1][0], bfr[p*2+1][1], addr);
                }
                // ---- A fragments + MMAs ----
#pragma unroll
                for (int mf = 0; mf < 2; ++mf) {
                    int row = wm * 32 + mf * 16 + (lane & 15);
                    int c   = sub * 2 + (lane >> 4);
                    uint32_t addr = ab + row * 256 + swz16(c, row);
                    uint32_t a0, a1, a2, a3;
                    ldmatrix_x4(a0, a1, a2, a3, addr);
#pragma unroll
                    for (int nf = 0; nf < 4; ++nf)
                        mma_tf32(acc[mf][nf][0], acc[mf][nf][1],
                                 acc[mf][nf][2], acc[mf][nf][3],
                                 a0, a1, a2, a3, bfr[nf][0], bfr[nf][1]);
                }
            }
        }
        __syncthreads();   // all HMMA smem reads done

        // Overlap: issue next chunk's stage-1 fill under the epilogue.
        if (ch + 1 < NCHUNK)
            fill_stage(sb, 1, 1, m0, n0 + BN, tid);

        // ---- epilogue: per-row top-4 over this chunk's 128 cols ----
        const int q = lane & 3;
#pragma unroll
        for (int mf = 0; mf < 2; ++mf) {
#pragma unroll
            for (int h = 0; h < 2; ++h) {
                float tb[4] = {-FLT_MAX, -FLT_MAX, -FLT_MAX, -FLT_MAX};
                int   ti[4] = {0x7fffffff, 0x7fffffff, 0x7fffffff, 0x7fffffff};
#pragma unroll
                for (int nf = 0; nf < 4; ++nf) {
                    int cloc = wn * 32 + nf * 8 + q * 2;
                    float s0 = acc[mf][nf][h*2+0] - 0.5f * e2s[cloc];
                    float s1 = acc[mf][nf][h*2+1] - 0.5f * e2s[cloc+1];
                    top4_upd(tb, ti, s0, n0 + cloc);
                    top4_upd(tb, ti, s1, n0 + cloc + 1);
                }
                // quad merge (lanes differing in bits 0,1 share the row)
#pragma unroll
                for (int o = 1; o <= 2; o <<= 1) {
#pragma unroll
                    for (int e = 0; e < 4; ++e) {
                        float os = __shfl_xor_sync(0xffffffffu, tb[e], o);
                        int   oi = __shfl_xor_sync(0xffffffffu, ti[e], o);
                        top4_upd(tb, ti, os, oi);
                    }
                }
                if (q == 0) {
                    int rl = wm * 32 + mf * 16 + h * 8 + (lane >> 2);
                    mbufS[rl * 4 + wn] = make_float4(tb[0], tb[1], tb[2], tb[3]);
                    mbufI[rl * 4 + wn] = make_int4(ti[0], ti[1], ti[2], ti[3]);
                }
            }
        }
        __syncthreads();
        if (tid < MT) {
#pragma unroll
            for (int w = 0; w < 4; ++w) {
                float4 s = mbufS[tid * 4 + w];
                int4   i = mbufI[tid * 4 + w];
                top4_upd(rb, ri, s.x, i.x);
                top4_upd(rb, ri, s.y, i.y);
                top4_upd(rb, ri, s.z, i.z);
                top4_upd(rb, ri, s.w, i.w);
            }
        }
        __syncthreads();   // protect e2s/mbuf before next chunk rewrites
    }

    if (tid < MT) g_top[m0 + tid] = make_int4(ri[0], ri[1], ri[2], ri[3]);
}

// ---------------------------------------------------------------------------
// Refine + gather: exact fp32 re-score of top-4, copy the winner row.
// ---------------------------------------------------------------------------
__global__ void refine_gather_kernel(const float* __restrict__ x,
                                     const float* __restrict__ emb,
                                     float* __restrict__ out) {
    int row  = (blockIdx.x * blockDim.x + threadIdx.x) >> 5;
    int lane = threadIdx.x & 31;
    int4 cnd = g_top[row];
    int idx[4] = {cnd.x, cnd.y, cnd.z, cnd.w};

    const float4* xr = reinterpret_cast<const float4*>(x + (size_t)row * DIM);
    float d[4] = {0.f, 0.f, 0.f, 0.f};
#pragma unroll
    for (int j = 0; j < 4; ++j) {
        float4 xv = xr[lane + j * 32];
#pragma unroll
        for (int cidx = 0; cidx < 4; ++cidx) {
            const float4* er = reinterpret_cast<const float4*>(
                emb + (size_t)idx[cidx] * DIM);
            float4 e = er[lane + j * 32];
            d[cidx] += xv.x * e.x + xv.y * e.y + xv.z * e.z + xv.w * e.w;
        }
    }
#pragma unroll
    for (int o = 16; o; o >>= 1)
#pragma unroll
        for (int cidx = 0; cidx < 4; ++cidx)
            d[cidx] += __shfl_xor_sync(0xffffffffu, d[cidx], o);

    float bs = d[0] - 0.5f * g_e2[idx[0]];
    int   bi = idx[0];
#pragma unroll
    for (int cidx = 1; cidx < 4; ++cidx) {
        float s = d[cidx] - 0.5f * g_e2[idx[cidx]];
        if (s > bs || (s == bs && idx[cidx] < bi)) { bs = s; bi = idx[cidx]; }
    }

    const float4* src = reinterpret_cast<const float4*>(emb + (size_t)bi * DIM);
    float4*       dst = reinterpret_cast<float4*>(out + (size_t)row * DIM);
#pragma unroll
    for (int j = 0; j < 4; ++j) dst[lane + j * 32] = src[lane + j * 32];
}

// ---------------------------------------------------------------------------
extern "C" void kernel_launch(void* const* d_in, const int* in_sizes, int n_in,
                              void* d_out, int out_size) {
    const float* x   = (const float*)d_in[0];
    const float* emb = (const float*)d_in[1];
    float*       out = (float*)d_out;

    cudaFuncSetAttribute(vq_main_kernel,
                         cudaFuncAttributeMaxDynamicSharedMemorySize, SMEM_TOTAL);

    e2_kernel<<<K_CODES / 8, 256>>>(emb);
    round_x_kernel<<<(M_TOTAL * DIM / 4) / 256, 256>>>(x);
    round_e_kernel<<<(K_CODES * DIM / 4) / 256, 256>>>(emb);
    vq_main_kernel<<<M_TOTAL / MT, NTHR, SMEM_TOTAL>>>();
    refine_gather_kernel<<<M_TOTAL / 8, 256>>>(x, emb, out);
}

// round 7
// speedup vs baseline: 2.9276x; 2.9276x over previous
#include <cuda_runtime.h>
#include <cuda_bf16.h>
#include <cstdint>
#include <cfloat>

// ---------------------------------------------------------------------------
// Problem constants
// ---------------------------------------------------------------------------
#define M_TOTAL 16384
#define K_CODES 8192
#define DIM     512
#define MT      64              // rows per CTA (2 CTAs/SM)
#define BN      128             // codes per chunk
#define NCHUNK  (K_CODES / BN)  // 64
#define BK      64              // bf16 K per B pipeline step (128 B/row)
#define KSTEPS  (DIM / BK)      // 8
#define NTHR    256

// ---------------------------------------------------------------------------
// Scratch (static device arrays: allocation-free rule)
// ---------------------------------------------------------------------------
__device__ __nv_bfloat16 g_Ab[(size_t)M_TOTAL * DIM];   // bf16(x)   16 MB
__device__ __nv_bfloat16 g_Bb[(size_t)K_CODES * DIM];   // bf16(emb)  8 MB
__device__ float g_e2[K_CODES];
__device__ int   g_top8[M_TOTAL][8];

// ---------------------------------------------------------------------------
// Baseline-PTX helpers (no "a"-suffix arch features)
// ---------------------------------------------------------------------------
__device__ __forceinline__ uint32_t smem_u32(const void* p) {
    uint32_t a;
    asm("{ .reg .u64 t; cvta.to.shared.u64 t, %1; cvt.u32.u64 %0, t; }"
        : "=r"(a) : "l"(p));
    return a;
}

__device__ __forceinline__ void cp_async16(uint32_t dst, const void* src) {
    uint64_t g;
    asm("cvta.to.global.u64 %0, %1;" : "=l"(g) : "l"(src));
    asm volatile("cp.async.cg.shared.global [%0], [%1], 16;"
                 :: "r"(dst), "l"(g) : "memory");
}
#define CP_COMMIT() asm volatile("cp.async.commit_group;" ::: "memory")

__device__ __forceinline__ void ldmatrix_x4(uint32_t& r0, uint32_t& r1,
                                            uint32_t& r2, uint32_t& r3,
                                            uint32_t addr) {
    asm volatile("ldmatrix.sync.aligned.m8n8.x4.shared.b16 {%0,%1,%2,%3}, [%4];"
                 : "=r"(r0), "=r"(r1), "=r"(r2), "=r"(r3) : "r"(addr));
}

__device__ __forceinline__ void mma_bf16(float& d0, float& d1, float& d2, float& d3,
                                         uint32_t a0, uint32_t a1, uint32_t a2, uint32_t a3,
                                         uint32_t b0, uint32_t b1) {
    asm volatile(
        "mma.sync.aligned.m16n8k16.row.col.f32.bf16.bf16.f32 "
        "{%0,%1,%2,%3}, {%4,%5,%6,%7}, {%8,%9}, {%0,%1,%2,%3};"
        : "+f"(d0), "+f"(d1), "+f"(d2), "+f"(d3)
        : "r"(a0), "r"(a1), "r"(a2), "r"(a3), "r"(b0), "r"(b1));
}

// ---------------------------------------------------------------------------
// SMEM layout: A persistent 64 KB + B 2x16 KB = 96 KB -> 2 CTAs/SM
// Final-merge buffer aliases the B region (only used after last chunk).
// ---------------------------------------------------------------------------
#define SM_A       0                          // 64 rows x 1024 B = 65536
#define SM_B       65536                      // 2 stages x 16384 (128 x 128 B)
#define B_STAGE    16384
#define SMEM_TOTAL (SM_B + 2 * B_STAGE)       // 98304

// ---------------------------------------------------------------------------
// Kernel: e2[k] = ||emb_k||^2 (exact fp32)
// ---------------------------------------------------------------------------
__global__ void e2_kernel(const float* __restrict__ emb) {
    int row  = blockIdx.x * 8 + (threadIdx.x >> 5);
    int lane = threadIdx.x & 31;
    const float4* p = reinterpret_cast<const float4*>(emb + (size_t)row * DIM);
    float s = 0.f;
#pragma unroll
    for (int i = 0; i < 4; ++i) {
        float4 v = p[lane + i * 32];
        s += v.x * v.x + v.y * v.y + v.z * v.z + v.w * v.w;
    }
#pragma unroll
    for (int o = 16; o; o >>= 1) s += __shfl_xor_sync(0xffffffffu, s, o);
    if (lane == 0) g_e2[row] = s;
}

// ---------------------------------------------------------------------------
// bf16 convert kernels
// ---------------------------------------------------------------------------
__global__ void cvt_x_kernel(const float* __restrict__ src) {
    size_t i = (size_t)blockIdx.x * 256 + threadIdx.x;   // float4 units
    float4 v = reinterpret_cast<const float4*>(src)[i];
    reinterpret_cast<__nv_bfloat162*>(g_Ab)[i * 2 + 0] = __floats2bfloat162_rn(v.x, v.y);
    reinterpret_cast<__nv_bfloat162*>(g_Ab)[i * 2 + 1] = __floats2bfloat162_rn(v.z, v.w);
}

__global__ void cvt_e_kernel(const float* __restrict__ src) {
    size_t i = (size_t)blockIdx.x * 256 + threadIdx.x;
    float4 v = reinterpret_cast<const float4*>(src)[i];
    reinterpret_cast<__nv_bfloat162*>(g_Bb)[i * 2 + 0] = __floats2bfloat162_rn(v.x, v.y);
    reinterpret_cast<__nv_bfloat162*>(g_Bb)[i * 2 + 1] = __floats2bfloat162_rn(v.z, v.w);
}

// ---------------------------------------------------------------------------
// Top-2 / Top-8 helpers (descending score, ascending index on ties)
// ---------------------------------------------------------------------------
__device__ __forceinline__ void top2_upd(float& b1, int& i1, float& b2, int& i2,
                                         float s, int idx) {
    if (s > b1 || (s == b1 && idx < i1)) { b2 = b1; i2 = i1; b1 = s; i1 = idx; }
    else if (s > b2 || (s == b2 && idx < i2)) { b2 = s; i2 = idx; }
}

__device__ __forceinline__ void top8_ins(float* b, int* ix, float s, int idx) {
    if (!(s > b[7] || (s == b[7] && idx < ix[7]))) return;
    int p = 7;
#pragma unroll
    for (int t = 0; t < 7; ++t) {
        if (p > 0 && (s > b[p-1] || (s == b[p-1] && idx < ix[p-1]))) {
            b[p] = b[p-1]; ix[p] = ix[p-1]; --p;
        }
    }
    b[p] = s; ix[p] = idx;
}

// ---------------------------------------------------------------------------
// B stage fill: 128 rows x 128 B, one commit group.
// ---------------------------------------------------------------------------
__device__ __forceinline__ void fill_B(uint32_t sb, int stage, int step,
                                       int n0, int tid) {
    const int gk = step * BK;
    uint32_t bb = sb + SM_B + stage * B_STAGE;
#pragma unroll
    for (int j = 0; j < 4; ++j) {
        int id = tid + j * 256;
        int row = id >> 3, c = id & 7;
        const void* src = g_Bb + (size_t)(n0 + row) * DIM + gk + c * 8;
        cp_async16(bb + row * 128 + ((c ^ (row & 7)) * 16), src);
    }
    CP_COMMIT();
}

// ---------------------------------------------------------------------------
// Main kernel: bf16 HMMA (A persistent in smem) + register top-2 per thread
// ---------------------------------------------------------------------------
__global__ void __launch_bounds__(NTHR, 2)
vq_main_kernel() {
    extern __shared__ char smem[];
    uint32_t sb = smem_u32(smem);

    const int tid  = threadIdx.x;
    const int lane = tid & 31;
    const int wid  = tid >> 5;
    const int wm   = wid >> 2;     // 0..1 (m half: 32 rows)
    const int wn   = wid & 3;      // 0..3 (n quarter: 32 cols)
    const int q    = lane & 3;
    const int m0   = blockIdx.x * MT;

    // ---- Prologue: load persistent A (64 x 512 bf16) + B chunk0 stage0/1 ----
#pragma unroll
    for (int j = 0; j < 16; ++j) {            // 4096 16B chunks
        int id = tid + j * 256;
        int row = id >> 6, c = id & 63;       // 64 chunks per 1024B row
        const void* src = g_Ab + (size_t)(m0 + row) * DIM + c * 8;
        uint32_t dst = sb + SM_A + row * 1024 + (c >> 3) * 128
                       + (((c & 7) ^ (row & 7)) * 16);
        cp_async16(dst, src);
    }
    fill_B(sb, 0, 0, 0, tid);                 // group G0 (includes A)
    fill_B(sb, 1, 1, 0, tid);                 // group G1

    // running per-thread top-2 for 4 row-slots [mf][h]
    float tb1[2][2], tb2[2][2];
    int   ti1[2][2], ti2[2][2];
#pragma unroll
    for (int a = 0; a < 2; ++a)
#pragma unroll
        for (int b = 0; b < 2; ++b) {
            tb1[a][b] = -FLT_MAX; tb2[a][b] = -FLT_MAX;
            ti1[a][b] = 0x7fffffff; ti2[a][b] = 0x7fffffff;
        }

#pragma unroll 1
    for (int ch = 0; ch < NCHUNK; ++ch) {
        const int n0 = ch * BN;

        // e2 for my 8 columns (L1-resident; no smem, no barrier)
        float e2v[8];
#pragma unroll
        for (int nf = 0; nf < 4; ++nf) {
            float2 p = *reinterpret_cast<const float2*>(
                &g_e2[n0 + wn * 32 + nf * 8 + q * 2]);
            e2v[nf * 2] = p.x; e2v[nf * 2 + 1] = p.y;
        }

        float acc[2][4][4];
#pragma unroll
        for (int a = 0; a < 2; ++a)
#pragma unroll
            for (int b = 0; b < 4; ++b)
#pragma unroll
                for (int c = 0; c < 4; ++c) acc[a][b][c] = 0.f;

#pragma unroll 1
        for (int st = 0; st < KSTEPS; ++st) {
            // Stage st&1 holds step st. At st=0 both st0,st1 groups are in
            // flight: wait only the older one.
            if (st == 0) asm volatile("cp.async.wait_group 1;" ::: "memory");
            else         asm volatile("cp.async.wait_group 0;" ::: "memory");
            __syncthreads();
            if (st >= 1 && st < KSTEPS - 1)
                fill_B(sb, (st + 1) & 1, st + 1, n0, tid);
            else if (st == KSTEPS - 1 && ch + 1 < NCHUNK)
                fill_B(sb, 0, 0, n0 + BN, tid);        // next chunk stage0

            const uint32_t bb = sb + SM_B + (st & 1) * B_STAGE;

#pragma unroll
            for (int sub = 0; sub < 4; ++sub) {        // 4 x k16 per BK=64
                // ---- B fragments (proven R4 pattern) ----
                uint32_t bfr[4][2];
#pragma unroll
                for (int p = 0; p < 2; ++p) {
                    int mi   = lane >> 3;
                    int noff = (mi >> 1) * 8;
                    int kc   = mi & 1;
                    int row  = wn * 32 + p * 16 + noff + (lane & 7);
                    int c    = sub * 2 + kc;
                    uint32_t addr = bb + row * 128 + ((c ^ (row & 7)) * 16);
                    ldmatrix_x4(bfr[p*2][0], bfr[p*2][1],
                                bfr[p*2+1][0], bfr[p*2+1][1], addr);
                }
                // ---- A fragments from persistent smem + MMAs ----
#pragma unroll
                for (int mf = 0; mf < 2; ++mf) {
                    int row = wm * 32 + mf * 16 + (lane & 15);
                    int cA  = (st * 4 + sub) * 2 + (lane >> 4);   // 0..63
                    uint32_t addr = sb + SM_A + row * 1024 + (cA >> 3) * 128
                                    + (((cA & 7) ^ (row & 7)) * 16);
                    uint32_t a0, a1, a2, a3;
                    ldmatrix_x4(a0, a1, a2, a3, addr);
#pragma unroll
                    for (int nf = 0; nf < 4; ++nf)
                        mma_bf16(acc[mf][nf][0], acc[mf][nf][1],
                                 acc[mf][nf][2], acc[mf][nf][3],
                                 a0, a1, a2, a3, bfr[nf][0], bfr[nf][1]);
                }
            }
        }
        __syncthreads();   // all warps done reading stage1 of this chunk

        // Overlap: next chunk's stage-1 fill under the (register) epilogue.
        if (ch + 1 < NCHUNK)
            fill_B(sb, 1, 1, n0 + BN, tid);

        // ---- epilogue: pure-register top-2 update, no barriers ----
#pragma unroll
        for (int mf = 0; mf < 2; ++mf)
#pragma unroll
            for (int h = 0; h < 2; ++h)
#pragma unroll
                for (int nf = 0; nf < 4; ++nf) {
                    int cloc = wn * 32 + nf * 8 + q * 2;
                    float s0 = acc[mf][nf][h*2+0] - 0.5f * e2v[nf*2+0];
                    float s1 = acc[mf][nf][h*2+1] - 0.5f * e2v[nf*2+1];
                    top2_upd(tb1[mf][h], ti1[mf][h], tb2[mf][h], ti2[mf][h],
                             s0, n0 + cloc);
                    top2_upd(tb1[mf][h], ti1[mf][h], tb2[mf][h], ti2[mf][h],
                             s1, n0 + cloc + 1);
                }
    }

    // ---- final merge: 16 threads x top-2 per row -> top-8 candidates ----
    __syncthreads();                       // B stages dead; alias merge buffer
    float4* mbuf = reinterpret_cast<float4*>(smem + SM_B);  // [64][16]
#pragma unroll
    for (int mf = 0; mf < 2; ++mf)
#pragma unroll
        for (int h = 0; h < 2; ++h) {
            int row = wm * 32 + mf * 16 + h * 8 + (lane >> 2);
            mbuf[row * 16 + wn * 4 + q] =
                make_float4(tb1[mf][h], tb2[mf][h],
                            __int_as_float(ti1[mf][h]),
                            __int_as_float(ti2[mf][h]));
        }
    __syncthreads();
    if (tid < MT) {
        float bs[8]; int bi[8];
#pragma unroll
        for (int e = 0; e < 8; ++e) { bs[e] = -FLT_MAX; bi[e] = 0x7fffffff; }
        for (int e = 0; e < 16; ++e) {
            float4 v = mbuf[tid * 16 + e];
            top8_ins(bs, bi, v.x, __float_as_int(v.z));
            top8_ins(bs, bi, v.y, __float_as_int(v.w));
        }
#pragma unroll
        for (int e = 0; e < 8; ++e) g_top8[m0 + tid][e] = bi[e];
    }
}

// ---------------------------------------------------------------------------
// Refine + gather: exact fp32 re-score of top-8, copy the winner row.
// ---------------------------------------------------------------------------
__global__ void refine_gather_kernel(const float* __restrict__ x,
                                     const float* __restrict__ emb,
                                     float* __restrict__ out) {
    int row  = (blockIdx.x * blockDim.x + threadIdx.x) >> 5;
    int lane = threadIdx.x & 31;
    int cand[8];
#pragma unroll
    for (int c = 0; c < 8; ++c) cand[c] = g_top8[row][c];

    const float4* xr = reinterpret_cast<const float4*>(x + (size_t)row * DIM);
    float d[8] = {0.f, 0.f, 0.f, 0.f, 0.f, 0.f, 0.f, 0.f};
#pragma unroll
    for (int j = 0; j < 4; ++j) {
        float4 xv = xr[lane + j * 32];
#pragma unroll
        for (int c = 0; c < 8; ++c) {
            const float4* er = reinterpret_cast<const float4*>(
                emb + (size_t)cand[c] * DIM);
            float4 e = er[lane + j * 32];
            d[c] += xv.x * e.x + xv.y * e.y + xv.z * e.z + xv.w * e.w;
        }
    }
#pragma unroll
    for (int o = 16; o; o >>= 1)
#pragma unroll
        for (int c = 0; c < 8; ++c)
            d[c] += __shfl_xor_sync(0xffffffffu, d[c], o);

    float bs = d[0] - 0.5f * g_e2[cand[0]];
    int   bi = cand[0];
#pragma unroll
    for (int c = 1; c < 8; ++c) {
        float s = d[c] - 0.5f * g_e2[cand[c]];
        if (s > bs || (s == bs && cand[c] < bi)) { bs = s; bi = cand[c]; }
    }

    const float4* src = reinterpret_cast<const float4*>(emb + (size_t)bi * DIM);
    float4*       dst = reinterpret_cast<float4*>(out + (size_t)row * DIM);
#pragma unroll
    for (int j = 0; j < 4; ++j) dst[lane + j * 32] = src[lane + j * 32];
}

// ---------------------------------------------------------------------------
extern "C" void kernel_launch(void* const* d_in, const int* in_sizes, int n_in,
                              void* d_out, int out_size) {
    const float* x   = (const float*)d_in[0];
    const float* emb = (const float*)d_in[1];
    float*       out = (float*)d_out;

    cudaFuncSetAttribute(vq_main_kernel,
                         cudaFuncAttributeMaxDynamicSharedMemorySize, SMEM_TOTAL);

    e2_kernel<<<K_CODES / 8, 256>>>(emb);
    cvt_x_kernel<<<(M_TOTAL * DIM / 4) / 256, 256>>>(x);
    cvt_e_kernel<<<(K_CODES * DIM / 4) / 256, 256>>>(emb);
    vq_main_kernel<<<M_TOTAL / MT, NTHR, SMEM_TOTAL>>>();
    refine_gather_kernel<<<M_TOTAL / 8, 256>>>(x, emb, out);
}

// round 8
// speedup vs baseline: 3.4740x; 1.1866x over previous
#include <cuda_runtime.h>
#include <cuda_bf16.h>
#include <cstdint>
#include <cfloat>

// ---------------------------------------------------------------------------
// Problem constants
// ---------------------------------------------------------------------------
#define M_TOTAL 16384
#define K_CODES 8192
#define DIM     512
#define MT      64              // rows per CTA (2 CTAs/SM)
#define BN      128             // codes per chunk
#define NCHUNK  (K_CODES / BN)  // 64
#define BK      64              // bf16 K per B pipeline step (128 B/row)
#define KSTEPS  (DIM / BK)      // 8
#define NTHR    256
#define IDXMASK 0x1FFFu         // 13 bits: code index embedded in mantissa

// ---------------------------------------------------------------------------
// Scratch (static device arrays: allocation-free rule)
// ---------------------------------------------------------------------------
__device__ __nv_bfloat16 g_Ab[(size_t)M_TOTAL * DIM];   // bf16(x)   16 MB
__device__ __nv_bfloat16 g_Bb[(size_t)K_CODES * DIM];   // bf16(emb)  8 MB
__device__ float g_e2[K_CODES];
__device__ int   g_top8[M_TOTAL][8];

// ---------------------------------------------------------------------------
// Baseline-PTX helpers (no "a"-suffix arch features)
// ---------------------------------------------------------------------------
__device__ __forceinline__ uint32_t smem_u32(const void* p) {
    uint32_t a;
    asm("{ .reg .u64 t; cvta.to.shared.u64 t, %1; cvt.u32.u64 %0, t; }"
        : "=r"(a) : "l"(p));
    return a;
}

__device__ __forceinline__ void cp_async16(uint32_t dst, const void* src) {
    uint64_t g;
    asm("cvta.to.global.u64 %0, %1;" : "=l"(g) : "l"(src));
    asm volatile("cp.async.cg.shared.global [%0], [%1], 16;"
                 :: "r"(dst), "l"(g) : "memory");
}
#define CP_COMMIT() asm volatile("cp.async.commit_group;" ::: "memory")

__device__ __forceinline__ void ldmatrix_x4(uint32_t& r0, uint32_t& r1,
                                            uint32_t& r2, uint32_t& r3,
                                            uint32_t addr) {
    asm volatile("ldmatrix.sync.aligned.m8n8.x4.shared.b16 {%0,%1,%2,%3}, [%4];"
                 : "=r"(r0), "=r"(r1), "=r"(r2), "=r"(r3) : "r"(addr));
}

__device__ __forceinline__ void mma_bf16(float& d0, float& d1, float& d2, float& d3,
                                         uint32_t a0, uint32_t a1, uint32_t a2, uint32_t a3,
                                         uint32_t b0, uint32_t b1) {
    asm volatile(
        "mma.sync.aligned.m16n8k16.row.col.f32.bf16.bf16.f32 "
        "{%0,%1,%2,%3}, {%4,%5,%6,%7}, {%8,%9}, {%0,%1,%2,%3};"
        : "+f"(d0), "+f"(d1), "+f"(d2), "+f"(d3)
        : "r"(a0), "r"(a1), "r"(a2), "r"(a3), "r"(b0), "r"(b1));
}

// Embed code index in low 13 mantissa bits (single LOP3). Perturbation
// <= |s| * 2^-11 -- absorbed by the exact top-8 refine.
__device__ __forceinline__ float embed_idx(float s, uint32_t idx) {
    uint32_t r;
    asm("lop3.b32 %0, %1, %2, %3, 0xEA;"     // (a & b) | c
        : "=r"(r) : "r"(__float_as_uint(s)), "r"(~IDXMASK), "r"(idx));
    return __uint_as_float(r);
}

// Branchless top-2 (values carry their index; tie semantics irrelevant).
__device__ __forceinline__ void top2f(float& b1, float& b2, float s) {
    float hi = fmaxf(b1, s);
    float lo = fminf(b1, s);
    b1 = hi;
    b2 = fmaxf(b2, lo);
}

// ---------------------------------------------------------------------------
// SMEM layout: A persistent 64 KB + B 2x16 KB = 96 KB -> 2 CTAs/SM
// Final-merge buffer aliases the B region (only used after last chunk).
// ---------------------------------------------------------------------------
#define SM_A       0                          // 64 rows x 1024 B = 65536
#define SM_B       65536                      // 2 stages x 16384 (128 x 128 B)
#define B_STAGE    16384
#define SMEM_TOTAL (SM_B + 2 * B_STAGE)       // 98304

// ---------------------------------------------------------------------------
// Kernel: e2[k] = ||emb_k||^2 (exact fp32)
// ---------------------------------------------------------------------------
__global__ void e2_kernel(const float* __restrict__ emb) {
    int row  = blockIdx.x * 8 + (threadIdx.x >> 5);
    int lane = threadIdx.x & 31;
    const float4* p = reinterpret_cast<const float4*>(emb + (size_t)row * DIM);
    float s = 0.f;
#pragma unroll
    for (int i = 0; i < 4; ++i) {
        float4 v = p[lane + i * 32];
        s += v.x * v.x + v.y * v.y + v.z * v.z + v.w * v.w;
    }
#pragma unroll
    for (int o = 16; o; o >>= 1) s += __shfl_xor_sync(0xffffffffu, s, o);
    if (lane == 0) g_e2[row] = s;
}

// ---------------------------------------------------------------------------
// bf16 convert kernels
// ---------------------------------------------------------------------------
__global__ void cvt_x_kernel(const float* __restrict__ src) {
    size_t i = (size_t)blockIdx.x * 256 + threadIdx.x;   // float4 units
    float4 v = reinterpret_cast<const float4*>(src)[i];
    reinterpret_cast<__nv_bfloat162*>(g_Ab)[i * 2 + 0] = __floats2bfloat162_rn(v.x, v.y);
    reinterpret_cast<__nv_bfloat162*>(g_Ab)[i * 2 + 1] = __floats2bfloat162_rn(v.z, v.w);
}

__global__ void cvt_e_kernel(const float* __restrict__ src) {
    size_t i = (size_t)blockIdx.x * 256 + threadIdx.x;
    float4 v = reinterpret_cast<const float4*>(src)[i];
    reinterpret_cast<__nv_bfloat162*>(g_Bb)[i * 2 + 0] = __floats2bfloat162_rn(v.x, v.y);
    reinterpret_cast<__nv_bfloat162*>(g_Bb)[i * 2 + 1] = __floats2bfloat162_rn(v.z, v.w);
}

// ---------------------------------------------------------------------------
// Top-8 insert on embedded-score floats (descending)
// ---------------------------------------------------------------------------
__device__ __forceinline__ void top8_ins(float* b, float s) {
    if (s <= b[7]) return;
    int p = 7;
#pragma unroll
    for (int t = 0; t < 7; ++t) {
        if (p > 0 && s > b[p - 1]) { b[p] = b[p - 1]; --p; }
    }
    b[p] = s;
}

// ---------------------------------------------------------------------------
// B stage fill: 128 rows x 128 B, one commit group.
// ---------------------------------------------------------------------------
__device__ __forceinline__ void fill_B(uint32_t sb, int stage, int step,
                                       int n0, int tid) {
    const int gk = step * BK;
    uint32_t bb = sb + SM_B + stage * B_STAGE;
#pragma unroll
    for (int j = 0; j < 4; ++j) {
        int id = tid + j * 256;
        int row = id >> 3, c = id & 7;
        const void* src = g_Bb + (size_t)(n0 + row) * DIM + gk + c * 8;
        cp_async16(bb + row * 128 + ((c ^ (row & 7)) * 16), src);
    }
    CP_COMMIT();
}

// ---------------------------------------------------------------------------
// Main kernel: bf16 HMMA (A persistent in smem) + embedded-index top-2
// ---------------------------------------------------------------------------
__global__ void __launch_bounds__(NTHR, 2)
vq_main_kernel() {
    extern __shared__ char smem[];
    uint32_t sb = smem_u32(smem);

    const int tid  = threadIdx.x;
    const int lane = tid & 31;
    const int wid  = tid >> 5;
    const int wm   = wid >> 2;     // 0..1 (m half: 32 rows)
    const int wn   = wid & 3;      // 0..3 (n quarter: 32 cols)
    const int q    = lane & 3;
    const int m0   = blockIdx.x * MT;

    // ---- Prologue: load persistent A (64 x 512 bf16) + B chunk0 stage0/1 ----
#pragma unroll
    for (int j = 0; j < 16; ++j) {            // 4096 16B chunks
        int id = tid + j * 256;
        int row = id >> 6, c = id & 63;       // 64 chunks per 1024B row
        const void* src = g_Ab + (size_t)(m0 + row) * DIM + c * 8;
        uint32_t dst = sb + SM_A + row * 1024 + (c >> 3) * 128
                       + (((c & 7) ^ (row & 7)) * 16);
        cp_async16(dst, src);
    }
    fill_B(sb, 0, 0, 0, tid);                 // group G0 (includes A)
    fill_B(sb, 1, 1, 0, tid);                 // group G1

    // running per-thread top-2 (embedded-index floats) for 4 row-slots
    float tb1[2][2], tb2[2][2];
#pragma unroll
    for (int a = 0; a < 2; ++a)
#pragma unroll
        for (int b = 0; b < 2; ++b) { tb1[a][b] = -FLT_MAX; tb2[a][b] = -FLT_MAX; }

#pragma unroll 1
    for (int ch = 0; ch < NCHUNK; ++ch) {
        const int n0 = ch * BN;

        // half-e2 for my 8 columns (L1-resident; no smem, no barrier)
        float e2h[8];
#pragma unroll
        for (int nf = 0; nf < 4; ++nf) {
            float2 p = *reinterpret_cast<const float2*>(
                &g_e2[n0 + wn * 32 + nf * 8 + q * 2]);
            e2h[nf * 2] = 0.5f * p.x; e2h[nf * 2 + 1] = 0.5f * p.y;
        }

        float acc[2][4][4];
#pragma unroll
        for (int a = 0; a < 2; ++a)
#pragma unroll
            for (int b = 0; b < 4; ++b)
#pragma unroll
                for (int c = 0; c < 4; ++c) acc[a][b][c] = 0.f;

#pragma unroll 1
        for (int st = 0; st < KSTEPS; ++st) {
            if (st == 0) asm volatile("cp.async.wait_group 1;" ::: "memory");
            else         asm volatile("cp.async.wait_group 0;" ::: "memory");
            __syncthreads();
            if (st >= 1 && st < KSTEPS - 1)
                fill_B(sb, (st + 1) & 1, st + 1, n0, tid);
            else if (st == KSTEPS - 1 && ch + 1 < NCHUNK)
                fill_B(sb, 0, 0, n0 + BN, tid);        // next chunk stage0

            const uint32_t bb = sb + SM_B + (st & 1) * B_STAGE;

#pragma unroll
            for (int sub = 0; sub < 4; ++sub) {        // 4 x k16 per BK=64
                // ---- B fragments (proven R4 pattern) ----
                uint32_t bfr[4][2];
#pragma unroll
                for (int p = 0; p < 2; ++p) {
                    int mi   = lane >> 3;
                    int noff = (mi >> 1) * 8;
                    int kc   = mi & 1;
                    int row  = wn * 32 + p * 16 + noff + (lane & 7);
                    int c    = sub * 2 + kc;
                    uint32_t addr = bb + row * 128 + ((c ^ (row & 7)) * 16);
                    ldmatrix_x4(bfr[p*2][0], bfr[p*2][1],
                                bfr[p*2+1][0], bfr[p*2+1][1], addr);
                }
                // ---- A fragments from persistent smem + MMAs ----
#pragma unroll
                for (int mf = 0; mf < 2; ++mf) {
                    int row = wm * 32 + mf * 16 + (lane & 15);
                    int cA  = (st * 4 + sub) * 2 + (lane >> 4);   // 0..63
                    uint32_t addr = sb + SM_A + row * 1024 + (cA >> 3) * 128
                                    + (((cA & 7) ^ (row & 7)) * 16);
                    uint32_t a0, a1, a2, a3;
                    ldmatrix_x4(a0, a1, a2, a3, addr);
#pragma unroll
                    for (int nf = 0; nf < 4; ++nf)
                        mma_bf16(acc[mf][nf][0], acc[mf][nf][1],
                                 acc[mf][nf][2], acc[mf][nf][3],
                                 a0, a1, a2, a3, bfr[nf][0], bfr[nf][1]);
                }
            }
        }
        __syncthreads();   // all warps done reading stage1 of this chunk

        // Overlap: next chunk's stage-1 fill under the (register) epilogue.
        if (ch + 1 < NCHUNK)
            fill_B(sb, 1, 1, n0 + BN, tid);

        // ---- epilogue: branchless embedded-index top-2, no barriers ----
#pragma unroll
        for (int mf = 0; mf < 2; ++mf)
#pragma unroll
            for (int h = 0; h < 2; ++h)
#pragma unroll
                for (int nf = 0; nf < 4; ++nf) {
                    uint32_t cloc = (uint32_t)(n0 + wn * 32 + nf * 8 + q * 2);
                    float s0 = embed_idx(acc[mf][nf][h*2+0] - e2h[nf*2+0], cloc);
                    float s1 = embed_idx(acc[mf][nf][h*2+1] - e2h[nf*2+1], cloc + 1);
                    top2f(tb1[mf][h], tb2[mf][h], s0);
                    top2f(tb1[mf][h], tb2[mf][h], s1);
                }
    }

    // ---- final merge: 16 threads x top-2 per row -> top-8 candidates ----
    __syncthreads();                       // B stages dead; alias merge buffer
    float2* mbuf = reinterpret_cast<float2*>(smem + SM_B);  // [64][16]
#pragma unroll
    for (int mf = 0; mf < 2; ++mf)
#pragma unroll
        for (int h = 0; h < 2; ++h) {
            int row = wm * 32 + mf * 16 + h * 8 + (lane >> 2);
            mbuf[row * 16 + wn * 4 + q] = make_float2(tb1[mf][h], tb2[mf][h]);
        }
    __syncthreads();
    if (tid < MT) {
        float bs[8];
#pragma unroll
        for (int e = 0; e < 8; ++e) bs[e] = -FLT_MAX;
        for (int e = 0; e < 16; ++e) {
            float2 v = mbuf[tid * 16 + e];
            top8_ins(bs, v.x);
            top8_ins(bs, v.y);
        }
#pragma unroll
        for (int e = 0; e < 8; ++e)
            g_top8[m0 + tid][e] = (int)(__float_as_uint(bs[e]) & IDXMASK);
    }
}

// ---------------------------------------------------------------------------
// Refine + gather: exact fp32 re-score of top-8, copy the winner row.
// ---------------------------------------------------------------------------
__global__ void refine_gather_kernel(const float* __restrict__ x,
                                     const float* __restrict__ emb,
                                     float* __restrict__ out) {
    int row  = (blockIdx.x * blockDim.x + threadIdx.x) >> 5;
    int lane = threadIdx.x & 31;
    int cand[8];
#pragma unroll
    for (int c = 0; c < 8; ++c) cand[c] = g_top8[row][c];

    const float4* xr = reinterpret_cast<const float4*>(x + (size_t)row * DIM);
    float d[8] = {0.f, 0.f, 0.f, 0.f, 0.f, 0.f, 0.f, 0.f};
#pragma unroll
    for (int j = 0; j < 4; ++j) {
        float4 xv = xr[lane + j * 32];
#pragma unroll
        for (int c = 0; c < 8; ++c) {
            const float4* er = reinterpret_cast<const float4*>(
                emb + (size_t)cand[c] * DIM);
            float4 e = er[lane + j * 32];
            d[c] += xv.x * e.x + xv.y * e.y + xv.z * e.z + xv.w * e.w;
        }
    }
#pragma unroll
    for (int o = 16; o; o >>= 1)
#pragma unroll
        for (int c = 0; c < 8; ++c)
            d[c] += __shfl_xor_sync(0xffffffffu, d[c], o);

    float bs = d[0] - 0.5f * g_e2[cand[0]];
    int   bi = cand[0];
#pragma unroll
    for (int c = 1; c < 8; ++c) {
        float s = d[c] - 0.5f * g_e2[cand[c]];
        if (s > bs || (s == bs && cand[c] < bi)) { bs = s; bi = cand[c]; }
    }

    const float4* src = reinterpret_cast<const float4*>(emb + (size_t)bi * DIM);
    float4*       dst = reinterpret_cast<float4*>(out + (size_t)row * DIM);
#pragma unroll
    for (int j = 0; j < 4; ++j) dst[lane + j * 32] = src[lane + j * 32];
}

// ---------------------------------------------------------------------------
extern "C" void kernel_launch(void* const* d_in, const int* in_sizes, int n_in,
                              void* d_out, int out_size) {
    const float* x   = (const float*)d_in[0];
    const float* emb = (const float*)d_in[1];
    float*       out = (float*)d_out;

    cudaFuncSetAttribute(vq_main_kernel,
                         cudaFuncAttributeMaxDynamicSharedMemorySize, SMEM_TOTAL);

    e2_kernel<<<K_CODES / 8, 256>>>(emb);
    cvt_x_kernel<<<(M_TOTAL * DIM / 4) / 256, 256>>>(x);
    cvt_e_kernel<<<(K_CODES * DIM / 4) / 256, 256>>>(emb);
    vq_main_kernel<<<M_TOTAL / MT, NTHR, SMEM_TOTAL>>>();
    refine_gather_kernel<<<M_TOTAL / 8, 256>>>(x, emb, out);
}

// round 9
// speedup vs baseline: 3.5345x; 1.0174x over previous
#include <cuda_runtime.h>
#include <cuda_bf16.h>
#include <cstdint>
#include <cfloat>

// ---------------------------------------------------------------------------
// Problem constants
// ---------------------------------------------------------------------------
#define M_TOTAL 16384
#define K_CODES 8192
#define DIM     512
#define MT      64              // rows per CTA (2 CTAs/SM)
#define BN      256             // codes per chunk (warp tile 32x64)
#define NCHUNK  (K_CODES / BN)  // 32
#define BK      32              // bf16 K per B pipeline step (64 B/row)
#define KSTEPS  (DIM / BK)      // 16
#define NTHR    256
#define IDXMASK 0x1FFFu         // 13 bits: code index embedded in mantissa

// ---------------------------------------------------------------------------
// Scratch (static device arrays: allocation-free rule)
// ---------------------------------------------------------------------------
__device__ __nv_bfloat16 g_Ab[(size_t)M_TOTAL * DIM];   // bf16(x)   16 MB
__device__ __nv_bfloat16 g_Bb[(size_t)K_CODES * DIM];   // bf16(emb)  8 MB
__device__ float g_e2[K_CODES];
__device__ int   g_top8[M_TOTAL][8];

// ---------------------------------------------------------------------------
// Baseline-PTX helpers (no "a"-suffix arch features)
// ---------------------------------------------------------------------------
__device__ __forceinline__ uint32_t smem_u32(const void* p) {
    uint32_t a;
    asm("{ .reg .u64 t; cvta.to.shared.u64 t, %1; cvt.u32.u64 %0, t; }"
        : "=r"(a) : "l"(p));
    return a;
}

__device__ __forceinline__ void cp_async16(uint32_t dst, const void* src) {
    uint64_t g;
    asm("cvta.to.global.u64 %0, %1;" : "=l"(g) : "l"(src));
    asm volatile("cp.async.cg.shared.global [%0], [%1], 16;"
                 :: "r"(dst), "l"(g) : "memory");
}
#define CP_COMMIT() asm volatile("cp.async.commit_group;" ::: "memory")

__device__ __forceinline__ void ldmatrix_x4(uint32_t& r0, uint32_t& r1,
                                            uint32_t& r2, uint32_t& r3,
                                            uint32_t addr) {
    asm volatile("ldmatrix.sync.aligned.m8n8.x4.shared.b16 {%0,%1,%2,%3}, [%4];"
                 : "=r"(r0), "=r"(r1), "=r"(r2), "=r"(r3) : "r"(addr));
}

__device__ __forceinline__ void mma_bf16(float& d0, float& d1, float& d2, float& d3,
                                         uint32_t a0, uint32_t a1, uint32_t a2, uint32_t a3,
                                         uint32_t b0, uint32_t b1) {
    asm volatile(
        "mma.sync.aligned.m16n8k16.row.col.f32.bf16.bf16.f32 "
        "{%0,%1,%2,%3}, {%4,%5,%6,%7}, {%8,%9}, {%0,%1,%2,%3};"
        : "+f"(d0), "+f"(d1), "+f"(d2), "+f"(d3)
        : "r"(a0), "r"(a1), "r"(a2), "r"(a3), "r"(b0), "r"(b1));
}

// Embed code index in low 13 mantissa bits (single LOP3). Perturbation
// <= |s| * 2^-11 -- absorbed by the exact top-8 refine.
__device__ __forceinline__ float embed_idx(float s, uint32_t idx) {
    uint32_t r;
    asm("lop3.b32 %0, %1, %2, %3, 0xEA;"     // (a & b) | c
        : "=r"(r) : "r"(__float_as_uint(s)), "r"(~IDXMASK), "r"(idx));
    return __uint_as_float(r);
}

// Branchless top-2 (values carry their index).
__device__ __forceinline__ void top2f(float& b1, float& b2, float s) {
    float hi = fmaxf(b1, s);
    float lo = fminf(b1, s);
    b1 = hi;
    b2 = fmaxf(b2, lo);
}

// ---------------------------------------------------------------------------
// SMEM layout: A persistent 64 KB + B 2x16 KB = 96 KB -> 2 CTAs/SM
// ---------------------------------------------------------------------------
#define SM_A       0                          // 64 rows x 1024 B = 65536
#define SM_B       65536                      // 2 stages x 16384 (256 x 64 B)
#define B_STAGE    16384
#define SMEM_TOTAL (SM_B + 2 * B_STAGE)       // 98304

// ---------------------------------------------------------------------------
// Kernel: e2[k] = ||emb_k||^2 (exact fp32)
// ---------------------------------------------------------------------------
__global__ void e2_kernel(const float* __restrict__ emb) {
    int row  = blockIdx.x * 8 + (threadIdx.x >> 5);
    int lane = threadIdx.x & 31;
    const float4* p = reinterpret_cast<const float4*>(emb + (size_t)row * DIM);
    float s = 0.f;
#pragma unroll
    for (int i = 0; i < 4; ++i) {
        float4 v = p[lane + i * 32];
        s += v.x * v.x + v.y * v.y + v.z * v.z + v.w * v.w;
    }
#pragma unroll
    for (int o = 16; o; o >>= 1) s += __shfl_xor_sync(0xffffffffu, s, o);
    if (lane == 0) g_e2[row] = s;
}

// ---------------------------------------------------------------------------
// bf16 convert kernels
// ---------------------------------------------------------------------------
__global__ void cvt_x_kernel(const float* __restrict__ src) {
    size_t i = (size_t)blockIdx.x * 256 + threadIdx.x;   // float4 units
    float4 v = reinterpret_cast<const float4*>(src)[i];
    reinterpret_cast<__nv_bfloat162*>(g_Ab)[i * 2 + 0] = __floats2bfloat162_rn(v.x, v.y);
    reinterpret_cast<__nv_bfloat162*>(g_Ab)[i * 2 + 1] = __floats2bfloat162_rn(v.z, v.w);
}

__global__ void cvt_e_kernel(const float* __restrict__ src) {
    size_t i = (size_t)blockIdx.x * 256 + threadIdx.x;
    float4 v = reinterpret_cast<const float4*>(src)[i];
    reinterpret_cast<__nv_bfloat162*>(g_Bb)[i * 2 + 0] = __floats2bfloat162_rn(v.x, v.y);
    reinterpret_cast<__nv_bfloat162*>(g_Bb)[i * 2 + 1] = __floats2bfloat162_rn(v.z, v.w);
}

// ---------------------------------------------------------------------------
// Top-8 insert on embedded-score floats (descending)
// ---------------------------------------------------------------------------
__device__ __forceinline__ void top8_ins(float* b, float s) {
    if (s <= b[7]) return;
    int p = 7;
#pragma unroll
    for (int t = 0; t < 7; ++t) {
        if (p > 0 && s > b[p - 1]) { b[p] = b[p - 1]; --p; }
    }
    b[p] = s;
}

// ---------------------------------------------------------------------------
// B stage fill: 256 rows x 64 B, one commit group.
// 64-B-row swizzle: chunk c at ((c ^ ((row>>1)&3)) * 16) -- 8-row ldmatrix
// reads hit 8 distinct 16B banks (even rows c^{0..3}, odd rows offset +4).
// ---------------------------------------------------------------------------
__device__ __forceinline__ void fill_B(uint32_t sb, int stage, int step,
                                       int n0, int tid) {
    const int gk = step * BK;
    uint32_t bb = sb + SM_B + stage * B_STAGE;
#pragma unroll
    for (int j = 0; j < 4; ++j) {
        int id = tid + j * 256;                // 1024 chunks: 256 rows x 4
        int row = id >> 2, c = id & 3;
        const void* src = g_Bb + (size_t)(n0 + row) * DIM + gk + c * 8;
        cp_async16(bb + row * 64 + ((c ^ ((row >> 1) & 3)) * 16), src);
    }
    CP_COMMIT();
}

// ---------------------------------------------------------------------------
// Main kernel: bf16 HMMA, warp tile 32x64 (mf=2, nf=8), A persistent in smem
// ---------------------------------------------------------------------------
__global__ void __launch_bounds__(NTHR, 2)
vq_main_kernel() {
    extern __shared__ char smem[];
    uint32_t sb = smem_u32(smem);

    const int tid  = threadIdx.x;
    const int lane = tid & 31;
    const int wid  = tid >> 5;
    const int wm   = wid >> 2;     // 0..1 (m half: 32 rows)
    const int wn   = wid & 3;      // 0..3 (n quarter: 64 cols)
    const int q    = lane & 3;
    const int m0   = blockIdx.x * MT;

    // ---- Prologue: persistent A (64 x 512 bf16) + B chunk0 stage0/1 ----
#pragma unroll
    for (int j = 0; j < 16; ++j) {            // 4096 16B chunks
        int id = tid + j * 256;
        int row = id >> 6, c = id & 63;       // 64 chunks per 1024B row
        const void* src = g_Ab + (size_t)(m0 + row) * DIM + c * 8;
        uint32_t dst = sb + SM_A + row * 1024 + (c >> 3) * 128
                       + (((c & 7) ^ (row & 7)) * 16);
        cp_async16(dst, src);
    }
    fill_B(sb, 0, 0, 0, tid);                 // group G0 (includes A)
    fill_B(sb, 1, 1, 0, tid);                 // group G1

    // running per-thread top-2 (embedded-index floats) for 4 row-slots
    float tb1[2][2], tb2[2][2];
#pragma unroll
    for (int a = 0; a < 2; ++a)
#pragma unroll
        for (int b = 0; b < 2; ++b) { tb1[a][b] = -FLT_MAX; tb2[a][b] = -FLT_MAX; }

#pragma unroll 1
    for (int ch = 0; ch < NCHUNK; ++ch) {
        const int n0 = ch * BN;

        float acc[2][8][4];
#pragma unroll
        for (int a = 0; a < 2; ++a)
#pragma unroll
            for (int b = 0; b < 8; ++b)
#pragma unroll
                for (int c = 0; c < 4; ++c) acc[a][b][c] = 0.f;

#pragma unroll 1
        for (int st = 0; st < KSTEPS; ++st) {
            if (st == 0) asm volatile("cp.async.wait_group 1;" ::: "memory");
            else         asm volatile("cp.async.wait_group 0;" ::: "memory");
            __syncthreads();
            if (st >= 1 && st < KSTEPS - 1)
                fill_B(sb, (st + 1) & 1, st + 1, n0, tid);
            else if (st == KSTEPS - 1 && ch + 1 < NCHUNK)
                fill_B(sb, 0, 0, n0 + BN, tid);        // next chunk stage0

            const uint32_t bb = sb + SM_B + (st & 1) * B_STAGE;

#pragma unroll
            for (int sub = 0; sub < 2; ++sub) {        // 2 x k16 per BK=32
                const int k16 = st * 2 + sub;
                // ---- A fragments (both mf) from persistent smem ----
                uint32_t afr[2][4];
#pragma unroll
                for (int mf = 0; mf < 2; ++mf) {
                    int row = wm * 32 + mf * 16 + (lane & 15);
                    int cA  = k16 * 2 + (lane >> 4);   // 0..63
                    uint32_t addr = sb + SM_A + row * 1024 + (cA >> 3) * 128
                                    + (((cA & 7) ^ (row & 7)) * 16);
                    ldmatrix_x4(afr[mf][0], afr[mf][1], afr[mf][2], afr[mf][3],
                                addr);
                }
                // ---- B in two nf-halves to cap register pressure ----
#pragma unroll
                for (int half = 0; half < 2; ++half) {
                    uint32_t bfr[4][2];
#pragma unroll
                    for (int pp = 0; pp < 2; ++pp) {
                        int p    = half * 2 + pp;      // 0..3, n offset p*16
                        int mi   = lane >> 3;
                        int noff = (mi >> 1) * 8;
                        int kc   = mi & 1;
                        int row  = wn * 64 + p * 16 + noff + (lane & 7);
                        int c    = sub * 2 + kc;       // 0..3
                        uint32_t addr = bb + row * 64
                                        + ((c ^ ((row >> 1) & 3)) * 16);
                        ldmatrix_x4(bfr[pp*2][0], bfr[pp*2][1],
                                    bfr[pp*2+1][0], bfr[pp*2+1][1], addr);
                    }
#pragma unroll
                    for (int mf = 0; mf < 2; ++mf)
#pragma unroll
                        for (int f = 0; f < 4; ++f) {
                            int nf = half * 4 + f;
                            mma_bf16(acc[mf][nf][0], acc[mf][nf][1],
                                     acc[mf][nf][2], acc[mf][nf][3],
                                     afr[mf][0], afr[mf][1],
                                     afr[mf][2], afr[mf][3],
                                     bfr[f][0], bfr[f][1]);
                        }
                }
            }
        }
        __syncthreads();   // all warps done reading stage1 of this chunk

        // Overlap: next chunk's stage-1 fill under the (register) epilogue.
        if (ch + 1 < NCHUNK)
            fill_B(sb, 1, 1, n0 + BN, tid);

        // ---- epilogue: branchless embedded-index top-2, no barriers ----
        float e2h[16];
#pragma unroll
        for (int nf = 0; nf < 8; ++nf) {
            float2 p = *reinterpret_cast<const float2*>(
                &g_e2[n0 + wn * 64 + nf * 8 + q * 2]);
            e2h[nf * 2] = 0.5f * p.x; e2h[nf * 2 + 1] = 0.5f * p.y;
        }
#pragma unroll
        for (int mf = 0; mf < 2; ++mf)
#pragma unroll
            for (int h = 0; h < 2; ++h)
#pragma unroll
                for (int nf = 0; nf < 8; ++nf) {
                    uint32_t cloc = (uint32_t)(n0 + wn * 64 + nf * 8 + q * 2);
                    float s0 = embed_idx(acc[mf][nf][h*2+0] - e2h[nf*2+0], cloc);
                    float s1 = embed_idx(acc[mf][nf][h*2+1] - e2h[nf*2+1], cloc + 1);
                    top2f(tb1[mf][h], tb2[mf][h], s0);
                    top2f(tb1[mf][h], tb2[mf][h], s1);
                }
    }

    // ---- final merge: 16 threads x top-2 per row -> top-8 candidates ----
    __syncthreads();                       // B stages dead; alias merge buffer
    float2* mbuf = reinterpret_cast<float2*>(smem + SM_B);  // [64][16]
#pragma unroll
    for (int mf = 0; mf < 2; ++mf)
#pragma unroll
        for (int h = 0; h < 2; ++h) {
            int row = wm * 32 + mf * 16 + h * 8 + (lane >> 2);
            mbuf[row * 16 + wn * 4 + q] = make_float2(tb1[mf][h], tb2[mf][h]);
        }
    __syncthreads();
    if (tid < MT) {
        float bs[8];
#pragma unroll
        for (int e = 0; e < 8; ++e) bs[e] = -FLT_MAX;
        for (int e = 0; e < 16; ++e) {
            float2 v = mbuf[tid * 16 + e];
            top8_ins(bs, v.x);
            top8_ins(bs, v.y);
        }
#pragma unroll
        for (int e = 0; e < 8; ++e)
            g_top8[m0 + tid][e] = (int)(__float_as_uint(bs[e]) & IDXMASK);
    }
}

// ---------------------------------------------------------------------------
// Refine + gather: exact fp32 re-score of top-8, copy the winner row.
// ---------------------------------------------------------------------------
__global__ void refine_gather_kernel(const float* __restrict__ x,
                                     const float* __restrict__ emb,
                                     float* __restrict__ out) {
    int row  = (blockIdx.x * blockDim.x + threadIdx.x) >> 5;
    int lane = threadIdx.x & 31;
    int cand[8];
#pragma unroll
    for (int c = 0; c < 8; ++c) cand[c] = g_top8[row][c];

    const float4* xr = reinterpret_cast<const float4*>(x + (size_t)row * DIM);
    float d[8] = {0.f, 0.f, 0.f, 0.f, 0.f, 0.f, 0.f, 0.f};
#pragma unroll
    for (int j = 0; j < 4; ++j) {
        float4 xv = xr[lane + j * 32];
#pragma unroll
        for (int c = 0; c < 8; ++c) {
            const float4* er = reinterpret_cast<const float4*>(
                emb + (size_t)cand[c] * DIM);
            float4 e = er[lane + j * 32];
            d[c] += xv.x * e.x + xv.y * e.y + xv.z * e.z + xv.w * e.w;
        }
    }
#pragma unroll
    for (int o = 16; o; o >>= 1)
#pragma unroll
        for (int c = 0; c < 8; ++c)
            d[c] += __shfl_xor_sync(0xffffffffu, d[c], o);

    float bs = d[0] - 0.5f * g_e2[cand[0]];
    int   bi = cand[0];
#pragma unroll
    for (int c = 1; c < 8; ++c) {
        float s = d[c] - 0.5f * g_e2[cand[c]];
        if (s > bs || (s == bs && cand[c] < bi)) { bs = s; bi = cand[c]; }
    }

    const float4* src = reinterpret_cast<const float4*>(emb + (size_t)bi * DIM);
    float4*       dst = reinterpret_cast<float4*>(out + (size_t)row * DIM);
#pragma unroll
    for (int j = 0; j < 4; ++j) dst[lane + j * 32] = src[lane + j * 32];
}

// ---------------------------------------------------------------------------
extern "C" void kernel_launch(void* const* d_in, const int* in_sizes, int n_in,
                              void* d_out, int out_size) {
    const float* x   = (const float*)d_in[0];
    const float* emb = (const float*)d_in[1];
    float*       out = (float*)d_out;

    cudaFuncSetAttribute(vq_main_kernel,
                         cudaFuncAttributeMaxDynamicSharedMemorySize, SMEM_TOTAL);

    e2_kernel<<<K_CODES / 8, 256>>>(emb);
    cvt_x_kernel<<<(M_TOTAL * DIM / 4) / 256, 256>>>(x);
    cvt_e_kernel<<<(K_CODES * DIM / 4) / 256, 256>>>(emb);
    vq_main_kernel<<<M_TOTAL / MT, NTHR, SMEM_TOTAL>>>();
    refine_gather_kernel<<<M_TOTAL / 8, 256>>>(x, emb, out);
}

// round 10
// speedup vs baseline: 3.6826x; 1.0419x over previous
#include <cuda_runtime.h>
#include <cuda_bf16.h>
#include <cstdint>
#include <cfloat>

// ---------------------------------------------------------------------------
// Problem constants
// ---------------------------------------------------------------------------
#define M_TOTAL 16384
#define K_CODES 8192
#define DIM     512
#define MT      64              // rows per CTA (2 CTAs/SM)
#define BN      256             // codes per chunk (warp tile 32x64)
#define NCHUNK  (K_CODES / BN)  // 32
#define BK      32              // bf16 K per B pipeline step (64 B/row)
#define KSTEPS  (DIM / BK)      // 16
#define NSTEPS  (NCHUNK * KSTEPS) // 512 global pipeline steps
#define NTHR    256
#define IDXMASK 0x1FFFu         // 13 bits: code index embedded in mantissa

// ---------------------------------------------------------------------------
// Scratch (static device arrays: allocation-free rule)
// ---------------------------------------------------------------------------
__device__ __nv_bfloat16 g_Ab[(size_t)M_TOTAL * DIM];   // bf16(x)   16 MB
__device__ __nv_bfloat16 g_Bb[(size_t)K_CODES * DIM];   // bf16(emb)  8 MB
__device__ float g_e2[K_CODES];
__device__ int   g_top8[M_TOTAL][8];

// ---------------------------------------------------------------------------
// Baseline-PTX helpers (no "a"-suffix arch features)
// ---------------------------------------------------------------------------
__device__ __forceinline__ uint32_t smem_u32(const void* p) {
    uint32_t a;
    asm("{ .reg .u64 t; cvta.to.shared.u64 t, %1; cvt.u32.u64 %0, t; }"
        : "=r"(a) : "l"(p));
    return a;
}

__device__ __forceinline__ void cp_async16(uint32_t dst, const void* src) {
    uint64_t g;
    asm("cvta.to.global.u64 %0, %1;" : "=l"(g) : "l"(src));
    asm volatile("cp.async.cg.shared.global [%0], [%1], 16;"
                 :: "r"(dst), "l"(g) : "memory");
}
#define CP_COMMIT() asm volatile("cp.async.commit_group;" ::: "memory")

__device__ __forceinline__ void ldmatrix_x4(uint32_t& r0, uint32_t& r1,
                                            uint32_t& r2, uint32_t& r3,
                                            uint32_t addr) {
    asm volatile("ldmatrix.sync.aligned.m8n8.x4.shared.b16 {%0,%1,%2,%3}, [%4];"
                 : "=r"(r0), "=r"(r1), "=r"(r2), "=r"(r3) : "r"(addr));
}

__device__ __forceinline__ void mma_bf16(float& d0, float& d1, float& d2, float& d3,
                                         uint32_t a0, uint32_t a1, uint32_t a2, uint32_t a3,
                                         uint32_t b0, uint32_t b1) {
    asm volatile(
        "mma.sync.aligned.m16n8k16.row.col.f32.bf16.bf16.f32 "
        "{%0,%1,%2,%3}, {%4,%5,%6,%7}, {%8,%9}, {%0,%1,%2,%3};"
        : "+f"(d0), "+f"(d1), "+f"(d2), "+f"(d3)
        : "r"(a0), "r"(a1), "r"(a2), "r"(a3), "r"(b0), "r"(b1));
}

// Named pair barrier: 2 warps (64 threads), ids 1..4.
__device__ __forceinline__ void bar_pair(int id) {
    asm volatile("bar.sync %0, 64;" :: "r"(id) : "memory");
}

// Embed code index in low 13 mantissa bits (single LOP3).
__device__ __forceinline__ float embed_idx(float s, uint32_t idx) {
    uint32_t r;
    asm("lop3.b32 %0, %1, %2, %3, 0xEA;"     // (a & b) | c
        : "=r"(r) : "r"(__float_as_uint(s)), "r"(~IDXMASK), "r"(idx));
    return __uint_as_float(r);
}

// Branchless top-2 (values carry their index).
__device__ __forceinline__ void top2f(float& b1, float& b2, float s) {
    float hi = fmaxf(b1, s);
    float lo = fminf(b1, s);
    b1 = hi;
    b2 = fmaxf(b2, lo);
}

// ---------------------------------------------------------------------------
// SMEM layout: A persistent 64 KB + B 3x16 KB = 112 KB -> 2 CTAs/SM
// Each B stage: 4 slices of 4 KB (one per wn pair).
// ---------------------------------------------------------------------------
#define SM_A       0                          // 64 rows x 1024 B = 65536
#define SM_B       65536                      // 3 stages x 16384 (256 x 64 B)
#define B_STAGE    16384
#define B_SLICE    4096
#define SMEM_TOTAL (SM_B + 3 * B_STAGE)       // 114688

// ---------------------------------------------------------------------------
// Kernel: e2[k] = ||emb_k||^2 (exact fp32)
// ---------------------------------------------------------------------------
__global__ void e2_kernel(const float* __restrict__ emb) {
    int row  = blockIdx.x * 8 + (threadIdx.x >> 5);
    int lane = threadIdx.x & 31;
    const float4* p = reinterpret_cast<const float4*>(emb + (size_t)row * DIM);
    float s = 0.f;
#pragma unroll
    for (int i = 0; i < 4; ++i) {
        float4 v = p[lane + i * 32];
        s += v.x * v.x + v.y * v.y + v.z * v.z + v.w * v.w;
    }
#pragma unroll
    for (int o = 16; o; o >>= 1) s += __shfl_xor_sync(0xffffffffu, s, o);
    if (lane == 0) g_e2[row] = s;
}

// ---------------------------------------------------------------------------
// bf16 convert kernels
// ---------------------------------------------------------------------------
__global__ void cvt_x_kernel(const float* __restrict__ src) {
    size_t i = (size_t)blockIdx.x * 256 + threadIdx.x;   // float4 units
    float4 v = reinterpret_cast<const float4*>(src)[i];
    reinterpret_cast<__nv_bfloat162*>(g_Ab)[i * 2 + 0] = __floats2bfloat162_rn(v.x, v.y);
    reinterpret_cast<__nv_bfloat162*>(g_Ab)[i * 2 + 1] = __floats2bfloat162_rn(v.z, v.w);
}

__global__ void cvt_e_kernel(const float* __restrict__ src) {
    size_t i = (size_t)blockIdx.x * 256 + threadIdx.x;
    float4 v = reinterpret_cast<const float4*>(src)[i];
    reinterpret_cast<__nv_bfloat162*>(g_Bb)[i * 2 + 0] = __floats2bfloat162_rn(v.x, v.y);
    reinterpret_cast<__nv_bfloat162*>(g_Bb)[i * 2 + 1] = __floats2bfloat162_rn(v.z, v.w);
}

// ---------------------------------------------------------------------------
// Top-8 insert on embedded-score floats (descending)
// ---------------------------------------------------------------------------
__device__ __forceinline__ void top8_ins(float* b, float s) {
    if (s <= b[7]) return;
    int p = 7;
#pragma unroll
    for (int t = 0; t < 7; ++t) {
        if (p > 0 && s > b[p - 1]) { b[p] = b[p - 1]; --p; }
    }
    b[p] = s;
}

// ---------------------------------------------------------------------------
// Pair-local B slice fill for global step gs: 64 rows x 64 B, 4 cp.async per
// thread (64 threads of the pair), one commit group.
// 64-B-row swizzle: chunk c at ((c ^ ((row>>1)&3)) * 16).
// ---------------------------------------------------------------------------
__device__ __forceinline__ void fill_slice(uint32_t sb, int gs, int wn, int pt) {
    const int ch = gs >> 4;                   // chunk
    const int st = gs & 15;                   // k-step within chunk
    const int n0 = ch * BN + wn * 64;
    const int gk = st * BK;
    uint32_t bb = sb + SM_B + (gs % 3) * B_STAGE + wn * B_SLICE;
#pragma unroll
    for (int j = 0; j < 4; ++j) {
        int id = pt + j * 64;                 // 256 chunks: 64 rows x 4
        int row = id >> 2, c = id & 3;
        const void* src = g_Bb + (size_t)(n0 + row) * DIM + gk + c * 8;
        cp_async16(bb + row * 64 + ((c ^ ((row >> 1) & 3)) * 16), src);
    }
    CP_COMMIT();
}

// ---------------------------------------------------------------------------
// Main kernel: bf16 HMMA, pair-local pipelines (no CTA barriers in k-loop)
// ---------------------------------------------------------------------------
__global__ void __launch_bounds__(NTHR, 2)
vq_main_kernel() {
    extern __shared__ char smem[];
    uint32_t sb = smem_u32(smem);

    const int tid  = threadIdx.x;
    const int lane = tid & 31;
    const int wid  = tid >> 5;
    const int wm   = wid >> 2;     // 0..1 (m half: 32 rows)
    const int wn   = wid & 3;      // 0..3 (n quarter: 64 cols)
    const int q    = lane & 3;
    const int pt   = wm * 32 + lane;   // 0..63 thread id within pair
    const int m0   = blockIdx.x * MT;

    // ---- Prologue: persistent A (group 0 with gs=0 fill) + gs=0, gs=1 ----
#pragma unroll
    for (int j = 0; j < 16; ++j) {            // 4096 16B chunks
        int id = tid + j * 256;
        int row = id >> 6, c = id & 63;       // 64 chunks per 1024B row
        const void* src = g_Ab + (size_t)(m0 + row) * DIM + c * 8;
        uint32_t dst = sb + SM_A + row * 1024 + (c >> 3) * 128
                       + (((c & 7) ^ (row & 7)) * 16);
        cp_async16(dst, src);
    }
    fill_slice(sb, 0, wn, pt);                // group G0 = A + step0 slice
    fill_slice(sb, 1, wn, pt);                // group G1 = step1 slice

    asm volatile("cp.async.wait_group 1;" ::: "memory");   // G0 (A + step0)
    __syncthreads();                          // A + everyone's step0 visible

    // running per-thread top-2 (embedded-index floats) for 4 row-slots
    float tb1[2][2], tb2[2][2];
#pragma unroll
    for (int a = 0; a < 2; ++a)
#pragma unroll
        for (int b = 0; b < 2; ++b) { tb1[a][b] = -FLT_MAX; tb2[a][b] = -FLT_MAX; }

#pragma unroll 1
    for (int ch = 0; ch < NCHUNK; ++ch) {
        const int n0 = ch * BN;

        float acc[2][8][4];
#pragma unroll
        for (int a = 0; a < 2; ++a)
#pragma unroll
            for (int b = 0; b < 8; ++b)
#pragma unroll
                for (int c = 0; c < 4; ++c) acc[a][b][c] = 0.f;

#pragma unroll 1
        for (int st = 0; st < KSTEPS; ++st) {
            const int gs = ch * KSTEPS + st;
            if (gs > 0) {
                // Complete own fill of stage gs%3 (leave gs+1's in flight).
                asm volatile("cp.async.wait_group 1;" ::: "memory");
                // Partner's half ready + partner done reading stage (gs-1)%3.
                bar_pair(wn + 1);
            }
            // Refill stage (gs+2)%3 = stage freed at end of step gs-1.
            if (gs + 2 < NSTEPS) fill_slice(sb, gs + 2, wn, pt);

            const uint32_t bb = sb + SM_B + (gs % 3) * B_STAGE + wn * B_SLICE;

#pragma unroll
            for (int sub = 0; sub < 2; ++sub) {        // 2 x k16 per BK=32
                const int k16 = st * 2 + sub;
                // ---- A fragments (both mf) from persistent smem ----
                uint32_t afr[2][4];
#pragma unroll
                for (int mf = 0; mf < 2; ++mf) {
                    int row = wm * 32 + mf * 16 + (lane & 15);
                    int cA  = k16 * 2 + (lane >> 4);   // 0..63
                    uint32_t addr = sb + SM_A + row * 1024 + (cA >> 3) * 128
                                    + (((cA & 7) ^ (row & 7)) * 16);
                    ldmatrix_x4(afr[mf][0], afr[mf][1], afr[mf][2], afr[mf][3],
                                addr);
                }
                // ---- B in two nf-halves to cap register pressure ----
#pragma unroll
                for (int half = 0; half < 2; ++half) {
                    uint32_t bfr[4][2];
#pragma unroll
                    for (int pp = 0; pp < 2; ++pp) {
                        int p    = half * 2 + pp;      // 0..3, n offset p*16
                        int mi   = lane >> 3;
                        int noff = (mi >> 1) * 8;
                        int kc   = mi & 1;
                        int rloc = p * 16 + noff + (lane & 7);   // 0..63
                        int c    = sub * 2 + kc;       // 0..3
                        uint32_t addr = bb + rloc * 64
                                        + ((c ^ ((rloc >> 1) & 3)) * 16);
                        ldmatrix_x4(bfr[pp*2][0], bfr[pp*2][1],
                                    bfr[pp*2+1][0], bfr[pp*2+1][1], addr);
                    }
#pragma unroll
                    for (int mf = 0; mf < 2; ++mf)
#pragma unroll
                        for (int f = 0; f < 4; ++f) {
                            int nf = half * 4 + f;
                            mma_bf16(acc[mf][nf][0], acc[mf][nf][1],
                                     acc[mf][nf][2], acc[mf][nf][3],
                                     afr[mf][0], afr[mf][1],
                                     afr[mf][2], afr[mf][3],
                                     bfr[f][0], bfr[f][1]);
                        }
                }
            }
        }

        // ---- epilogue: branchless embedded-index top-2, no barriers ----
        float e2h[16];
#pragma unroll
        for (int nf = 0; nf < 8; ++nf) {
            float2 p = *reinterpret_cast<const float2*>(
                &g_e2[n0 + wn * 64 + nf * 8 + q * 2]);
            e2h[nf * 2] = 0.5f * p.x; e2h[nf * 2 + 1] = 0.5f * p.y;
        }
#pragma unroll
        for (int mf = 0; mf < 2; ++mf)
#pragma unroll
            for (int h = 0; h < 2; ++h)
#pragma unroll
                for (int nf = 0; nf < 8; ++nf) {
                    uint32_t cloc = (uint32_t)(n0 + wn * 64 + nf * 8 + q * 2);
                    float s0 = embed_idx(acc[mf][nf][h*2+0] - e2h[nf*2+0], cloc);
                    float s1 = embed_idx(acc[mf][nf][h*2+1] - e2h[nf*2+1], cloc + 1);
                    top2f(tb1[mf][h], tb2[mf][h], s0);
                    top2f(tb1[mf][h], tb2[mf][h], s1);
                }
    }

    // ---- final merge: 16 threads x top-2 per row -> top-8 candidates ----
    __syncthreads();                       // B stages dead; alias merge buffer
    float2* mbuf = reinterpret_cast<float2*>(smem + SM_B);  // [64][16]
#pragma unroll
    for (int mf = 0; mf < 2; ++mf)
#pragma unroll
        for (int h = 0; h < 2; ++h) {
            int row = wm * 32 + mf * 16 + h * 8 + (lane >> 2);
            mbuf[row * 16 + wn * 4 + q] = make_float2(tb1[mf][h], tb2[mf][h]);
        }
    __syncthreads();
    if (tid < MT) {
        float bs[8];
#pragma unroll
        for (int e = 0; e < 8; ++e) bs[e] = -FLT_MAX;
        for (int e = 0; e < 16; ++e) {
            float2 v = mbuf[tid * 16 + e];
            top8_ins(bs, v.x);
            top8_ins(bs, v.y);
        }
#pragma unroll
        for (int e = 0; e < 8; ++e)
            g_top8[m0 + tid][e] = (int)(__float_as_uint(bs[e]) & IDXMASK);
    }
}

// ---------------------------------------------------------------------------
// Refine + gather: exact fp32 re-score of top-8, copy the winner row.
// ---------------------------------------------------------------------------
__global__ void refine_gather_kernel(const float* __restrict__ x,
                                     const float* __restrict__ emb,
                                     float* __restrict__ out) {
    int row  = (blockIdx.x * blockDim.x + threadIdx.x) >> 5;
    int lane = threadIdx.x & 31;
    int cand[8];
#pragma unroll
    for (int c = 0; c < 8; ++c) cand[c] = g_top8[row][c];

    const float4* xr = reinterpret_cast<const float4*>(x + (size_t)row * DIM);
    float d[8] = {0.f, 0.f, 0.f, 0.f, 0.f, 0.f, 0.f, 0.f};
#pragma unroll
    for (int j = 0; j < 4; ++j) {
        float4 xv = xr[lane + j * 32];
#pragma unroll
        for (int c = 0; c < 8; ++c) {
            const float4* er = reinterpret_cast<const float4*>(
                emb + (size_t)cand[c] * DIM);
            float4 e = er[lane + j * 32];
            d[c] += xv.x * e.x + xv.y * e.y + xv.z * e.z + xv.w * e.w;
        }
    }
#pragma unroll
    for (int o = 16; o; o >>= 1)
#pragma unroll
        for (int c = 0; c < 8; ++c)
            d[c] += __shfl_xor_sync(0xffffffffu, d[c], o);

    float bs = d[0] - 0.5f * g_e2[cand[0]];
    int   bi = cand[0];
#pragma unroll
    for (int c = 1; c < 8; ++c) {
        float s = d[c] - 0.5f * g_e2[cand[c]];
        if (s > bs || (s == bs && cand[c] < bi)) { bs = s; bi = cand[c]; }
    }

    const float4* src = reinterpret_cast<const float4*>(emb + (size_t)bi * DIM);
    float4*       dst = reinterpret_cast<float4*>(out + (size_t)row * DIM);
#pragma unroll
    for (int j = 0; j < 4; ++j) dst[lane + j * 32] = src[lane + j * 32];
}

// ---------------------------------------------------------------------------
extern "C" void kernel_launch(void* const* d_in, const int* in_sizes, int n_in,
                              void* d_out, int out_size) {
    const float* x   = (const float*)d_in[0];
    const float* emb = (const float*)d_in[1];
    float*       out = (float*)d_out;

    cudaFuncSetAttribute(vq_main_kernel,
                         cudaFuncAttributeMaxDynamicSharedMemorySize, SMEM_TOTAL);

    e2_kernel<<<K_CODES / 8, 256>>>(emb);
    cvt_x_kernel<<<(M_TOTAL * DIM / 4) / 256, 256>>>(x);
    cvt_e_kernel<<<(K_CODES * DIM / 4) / 256, 256>>>(emb);
    vq_main_kernel<<<M_TOTAL / MT, NTHR, SMEM_TOTAL>>>();
    refine_gather_kernel<<<M_TOTAL / 8, 256>>>(x, emb, out);
}

// round 11
// speedup vs baseline: 4.0954x; 1.1121x over previous
#include <cuda_runtime.h>
#include <cuda_bf16.h>
#include <cstdint>
#include <cfloat>

// ---------------------------------------------------------------------------
// Problem constants
// ---------------------------------------------------------------------------
#define M_TOTAL 16384
#define K_CODES 8192
#define DIM     512
#define MT      64              // rows per CTA (2 CTAs/SM)
#define BN      256             // codes per chunk; warp tile 64x32
#define NCHUNK  (K_CODES / BN)  // 32
#define BK      32              // bf16 K per pipeline step (64 B/row)
#define KSTEPS  (DIM / BK)      // 16
#define NSTEPS  (NCHUNK * KSTEPS) // 512
#define NTHR    256
#define IDXMASK 0x1FFFu         // 13 bits: code index embedded in mantissa

// ---------------------------------------------------------------------------
// Scratch (static device arrays: allocation-free rule)
// ---------------------------------------------------------------------------
__device__ __nv_bfloat16 g_Ab[(size_t)M_TOTAL * DIM];   // bf16(x)   16 MB
__device__ __nv_bfloat16 g_Bb[(size_t)K_CODES * DIM];   // bf16(emb)  8 MB
__device__ float g_e2[K_CODES];
__device__ int   g_top8[M_TOTAL][8];

// ---------------------------------------------------------------------------
// Baseline-PTX helpers (no "a"-suffix arch features)
// ---------------------------------------------------------------------------
__device__ __forceinline__ uint32_t smem_u32(const void* p) {
    uint32_t a;
    asm("{ .reg .u64 t; cvta.to.shared.u64 t, %1; cvt.u32.u64 %0, t; }"
        : "=r"(a) : "l"(p));
    return a;
}

__device__ __forceinline__ void cp_async16(uint32_t dst, const void* src) {
    uint64_t g;
    asm("cvta.to.global.u64 %0, %1;" : "=l"(g) : "l"(src));
    asm volatile("cp.async.cg.shared.global [%0], [%1], 16;"
                 :: "r"(dst), "l"(g) : "memory");
}

// Pre-converted global address variant (no per-call cvta).
__device__ __forceinline__ void cp_async16g(uint32_t dst, uint64_t gsrc) {
    asm volatile("cp.async.cg.shared.global [%0], [%1], 16;"
                 :: "r"(dst), "l"(gsrc) : "memory");
}
#define CP_COMMIT() asm volatile("cp.async.commit_group;" ::: "memory")

__device__ __forceinline__ void ldmatrix_x4(uint32_t& r0, uint32_t& r1,
                                            uint32_t& r2, uint32_t& r3,
                                            uint32_t addr) {
    asm volatile("ldmatrix.sync.aligned.m8n8.x4.shared.b16 {%0,%1,%2,%3}, [%4];"
                 : "=r"(r0), "=r"(r1), "=r"(r2), "=r"(r3) : "r"(addr));
}

__device__ __forceinline__ void mma_bf16(float& d0, float& d1, float& d2, float& d3,
                                         uint32_t a0, uint32_t a1, uint32_t a2, uint32_t a3,
                                         uint32_t b0, uint32_t b1) {
    asm volatile(
        "mma.sync.aligned.m16n8k16.row.col.f32.bf16.bf16.f32 "
        "{%0,%1,%2,%3}, {%4,%5,%6,%7}, {%8,%9}, {%0,%1,%2,%3};"
        : "+f"(d0), "+f"(d1), "+f"(d2), "+f"(d3)
        : "r"(a0), "r"(a1), "r"(a2), "r"(a3), "r"(b0), "r"(b1));
}

// Embed code index in low 13 mantissa bits (single LOP3).
__device__ __forceinline__ float embed_idx(float s, uint32_t idx) {
    uint32_t r;
    asm("lop3.b32 %0, %1, %2, %3, 0xEA;"     // (a & b) | c
        : "=r"(r) : "r"(__float_as_uint(s)), "r"(~IDXMASK), "r"(idx));
    return __uint_as_float(r);
}

// Branchless top-2 (values carry their index).
__device__ __forceinline__ void top2f(float& b1, float& b2, float s) {
    float hi = fmaxf(b1, s);
    float lo = fminf(b1, s);
    b1 = hi;
    b2 = fmaxf(b2, lo);
}

// ---------------------------------------------------------------------------
// SMEM layout: A persistent 64 KB + B 3 stages x 16 KB -> 112 KB, 2 CTAs/SM.
// Each B stage = 8 warp-private slices of 2 KB (32 rows x 64 B).
// ---------------------------------------------------------------------------
#define SM_A       0                          // 64 rows x 1024 B
#define SM_B       65536
#define B_STAGE    16384
#define W_SLICE    2048
#define SMEM_TOTAL (SM_B + 3 * B_STAGE)       // 114688

// ---------------------------------------------------------------------------
// Kernel: e2[k] = ||emb_k||^2 (exact fp32)
// ---------------------------------------------------------------------------
__global__ void e2_kernel(const float* __restrict__ emb) {
    int row  = blockIdx.x * 8 + (threadIdx.x >> 5);
    int lane = threadIdx.x & 31;
    const float4* p = reinterpret_cast<const float4*>(emb + (size_t)row * DIM);
    float s = 0.f;
#pragma unroll
    for (int i = 0; i < 4; ++i) {
        float4 v = p[lane + i * 32];
        s += v.x * v.x + v.y * v.y + v.z * v.z + v.w * v.w;
    }
#pragma unroll
    for (int o = 16; o; o >>= 1) s += __shfl_xor_sync(0xffffffffu, s, o);
    if (lane == 0) g_e2[row] = s;
}

// ---------------------------------------------------------------------------
// bf16 convert kernels
// ---------------------------------------------------------------------------
__global__ void cvt_x_kernel(const float* __restrict__ src) {
    size_t i = (size_t)blockIdx.x * 256 + threadIdx.x;   // float4 units
    float4 v = reinterpret_cast<const float4*>(src)[i];
    reinterpret_cast<__nv_bfloat162*>(g_Ab)[i * 2 + 0] = __floats2bfloat162_rn(v.x, v.y);
    reinterpret_cast<__nv_bfloat162*>(g_Ab)[i * 2 + 1] = __floats2bfloat162_rn(v.z, v.w);
}

__global__ void cvt_e_kernel(const float* __restrict__ src) {
    size_t i = (size_t)blockIdx.x * 256 + threadIdx.x;
    float4 v = reinterpret_cast<const float4*>(src)[i];
    reinterpret_cast<__nv_bfloat162*>(g_Bb)[i * 2 + 0] = __floats2bfloat162_rn(v.x, v.y);
    reinterpret_cast<__nv_bfloat162*>(g_Bb)[i * 2 + 1] = __floats2bfloat162_rn(v.z, v.w);
}

// ---------------------------------------------------------------------------
// Top-8 insert on embedded-score floats (descending)
// ---------------------------------------------------------------------------
__device__ __forceinline__ void top8_ins(float* b, float s) {
    if (s <= b[7]) return;
    int p = 7;
#pragma unroll
    for (int t = 0; t < 7; ++t) {
        if (p > 0 && s > b[p - 1]) { b[p] = b[p - 1]; --p; }
    }
    b[p] = s;
}

// ---------------------------------------------------------------------------
// Main kernel: bf16 HMMA, warp tile 64x32, fully warp-private B pipelines.
// No bar.sync anywhere in the k-loop.
// ---------------------------------------------------------------------------
__global__ void __launch_bounds__(NTHR, 2)
vq_main_kernel() {
    extern __shared__ char smem[];
    uint32_t sb = smem_u32(smem);

    const int tid  = threadIdx.x;
    const int lane = tid & 31;
    const int w    = tid >> 5;     // warp 0..7: owns codes [w*32, w*32+32) per chunk
    const int q    = lane & 3;
    const int m0   = blockIdx.x * MT;

    // ---- Prologue: persistent A (cooperative; part of group G0) ----
#pragma unroll
    for (int j = 0; j < 16; ++j) {            // 4096 16B chunks
        int id = tid + j * 256;
        int row = id >> 6, c = id & 63;       // 64 chunks per 1024B row
        const void* src = g_Ab + (size_t)(m0 + row) * DIM + c * 8;
        uint32_t dst = sb + SM_A + row * 1024 + (c >> 3) * 128
                       + (((c & 7) ^ (row & 7)) * 16);
        cp_async16(dst, src);
    }

    // Per-thread B-fill constants. Thread covers rows row0+8j (j=0..3), chunk c0.
    // swz is j-invariant: ((row0+8j)>>1)&3 == (row0>>1)&3.
    const int row0 = lane >> 2;               // 0..7
    const int c0   = lane & 3;
    uint64_t gB;
    asm("cvta.to.global.u64 %0, %1;" : "=l"(gB) : "l"(g_Bb));
    const uint64_t pbase = gB
        + (uint32_t)(((w * 32 + row0) * 512 + c0 * 8) * 2);           // bytes
    const uint32_t d0 = (uint32_t)(w * W_SLICE + row0 * 64
                                   + ((c0 ^ ((row0 >> 1) & 3)) * 16));

    // Fill gs=0 (group G0, with A) and gs=1 (G1). gs: ch=gs>>4, st=gs&15.
    {
        uint32_t fb = sb + SM_B + 0 * B_STAGE + d0;
#pragma unroll
        for (int j = 0; j < 4; ++j) cp_async16g(fb + j * 512, pbase + j * 8192);
        CP_COMMIT();
    }
    {
        uint32_t fb = sb + SM_B + 1 * B_STAGE + d0;
#pragma unroll
        for (int j = 0; j < 4; ++j) cp_async16g(fb + j * 512, pbase + 64 + j * 8192);
        CP_COMMIT();
    }

    asm volatile("cp.async.wait_group 1;" ::: "memory");   // G0: A + slice0
    __syncthreads();                                       // A visible to all

    // per-thread running top-2 (embedded-index floats) for 8 row-slots [mf][h]
    float tb1[4][2], tb2[4][2];
#pragma unroll
    for (int a = 0; a < 4; ++a)
#pragma unroll
        for (int b = 0; b < 2; ++b) { tb1[a][b] = -FLT_MAX; tb2[a][b] = -FLT_MAX; }

    int sr = 0;                                // gs % 3
#pragma unroll 1
    for (int ch = 0; ch < NCHUNK; ++ch) {
        const int n0 = ch * BN;

        float acc[4][4][4];
#pragma unroll
        for (int a = 0; a < 4; ++a)
#pragma unroll
            for (int b = 0; b < 4; ++b)
#pragma unroll
                for (int c = 0; c < 4; ++c) acc[a][b][c] = 0.f;

#pragma unroll 1
        for (int st = 0; st < KSTEPS; ++st) {
            const int gs = ch * KSTEPS + st;

            // ---- A fragments for sub 0 (persistent smem; no dependency) ----
            uint32_t afr[4][4];
#pragma unroll
            for (int mf = 0; mf < 4; ++mf) {
                int row = mf * 16 + (lane & 15);
                int cA  = (st * 2) * 2 + (lane >> 4);   // k16 = st*2
                uint32_t addr = sb + SM_A + row * 1024 + (cA >> 3) * 128
                                + (((cA & 7) ^ (row & 7)) * 16);
                ldmatrix_x4(afr[mf][0], afr[mf][1], afr[mf][2], afr[mf][3], addr);
            }

            // Own fill of stage gs%3 complete (fill gs+1 may stay in flight).
            asm volatile("cp.async.wait_group 1;" ::: "memory");

            // Refill stage (gs+2)%3 (this warp finished reading it at gs-1).
            const int sf = (sr >= 1) ? (sr - 1) : 2;
            if (gs + 2 < NSTEPS) {
                const int g2 = gs + 2;
                uint64_t src = pbase
                    + (uint32_t)(((g2 >> 4) << 18) + ((g2 & 15) << 6));
                uint32_t fb = sb + SM_B + sf * B_STAGE + d0;
#pragma unroll
                for (int j = 0; j < 4; ++j)
                    cp_async16g(fb + j * 512, src + j * 8192);
                CP_COMMIT();
            } else {
                CP_COMMIT();           // keep group arithmetic uniform
            }

            const uint32_t bb = sb + SM_B + sr * B_STAGE + w * W_SLICE;

#pragma unroll
            for (int sub = 0; sub < 2; ++sub) {        // 2 x k16 per BK=32
                if (sub == 1) {
                    // A fragments for sub 1 (reuse afr registers)
#pragma unroll
                    for (int mf = 0; mf < 4; ++mf) {
                        int row = mf * 16 + (lane & 15);
                        int cA  = (st * 2 + 1) * 2 + (lane >> 4);
                        uint32_t addr = sb + SM_A + row * 1024 + (cA >> 3) * 128
                                        + (((cA & 7) ^ (row & 7)) * 16);
                        ldmatrix_x4(afr[mf][0], afr[mf][1],
                                    afr[mf][2], afr[mf][3], addr);
                    }
                }
                // ---- B fragments: 4 n-frags (8 codes each) = 2 ldmatrix.x4 ----
                uint32_t bfr[4][2];
#pragma unroll
                for (int p = 0; p < 2; ++p) {
                    int mi   = lane >> 3;
                    int noff = (mi >> 1) * 8;
                    int kc   = mi & 1;
                    int rloc = p * 16 + noff + (lane & 7);   // 0..31
                    int c    = sub * 2 + kc;
                    uint32_t addr = bb + rloc * 64
                                    + ((c ^ ((rloc >> 1) & 3)) * 16);
                    ldmatrix_x4(bfr[p*2][0], bfr[p*2][1],
                                bfr[p*2+1][0], bfr[p*2+1][1], addr);
                }
#pragma unroll
                for (int mf = 0; mf < 4; ++mf)
#pragma unroll
                    for (int nf = 0; nf < 4; ++nf)
                        mma_bf16(acc[mf][nf][0], acc[mf][nf][1],
                                 acc[mf][nf][2], acc[mf][nf][3],
                                 afr[mf][0], afr[mf][1], afr[mf][2], afr[mf][3],
                                 bfr[nf][0], bfr[nf][1]);
            }
            sr = (sr == 2) ? 0 : sr + 1;
        }

        // ---- epilogue: branchless embedded-index top-2 (no barriers) ----
        float e2h[8];
#pragma unroll
        for (int nf = 0; nf < 4; ++nf) {
            float2 p = *reinterpret_cast<const float2*>(
                &g_e2[n0 + w * 32 + nf * 8 + q * 2]);
            e2h[nf * 2] = 0.5f * p.x; e2h[nf * 2 + 1] = 0.5f * p.y;
        }
#pragma unroll
        for (int mf = 0; mf < 4; ++mf)
#pragma unroll
            for (int h = 0; h < 2; ++h)
#pragma unroll
                for (int nf = 0; nf < 4; ++nf) {
                    uint32_t cloc = (uint32_t)(n0 + w * 32 + nf * 8 + q * 2);
                    float s0 = embed_idx(acc[mf][nf][h*2+0] - e2h[nf*2+0], cloc);
                    float s1 = embed_idx(acc[mf][nf][h*2+1] - e2h[nf*2+1], cloc + 1);
                    top2f(tb1[mf][h], tb2[mf][h], s0);
                    top2f(tb1[mf][h], tb2[mf][h], s1);
                }
    }

    // ---- final merge: 32 contributors x top-2 per row -> top-8 ----
    asm volatile("cp.async.wait_group 0;" ::: "memory");   // drain tail groups
    __syncthreads();                       // B stages dead; alias merge buffer
    float2* mbuf = reinterpret_cast<float2*>(smem + SM_B); // [64 rows][32]
#pragma unroll
    for (int mf = 0; mf < 4; ++mf)
#pragma unroll
        for (int h = 0; h < 2; ++h) {
            int row = mf * 16 + h * 8 + (lane >> 2);
            mbuf[row * 32 + w * 4 + q] = make_float2(tb1[mf][h], tb2[mf][h]);
        }
    __syncthreads();
    if (tid < MT) {
        float bs[8];
#pragma unroll
        for (int e = 0; e < 8; ++e) bs[e] = -FLT_MAX;
        for (int e = 0; e < 32; ++e) {
            float2 v = mbuf[tid * 32 + e];
            top8_ins(bs, v.x);
            top8_ins(bs, v.y);
        }
#pragma unroll
        for (int e = 0; e < 8; ++e)
            g_top8[m0 + tid][e] = (int)(__float_as_uint(bs[e]) & IDXMASK);
    }
}

// ---------------------------------------------------------------------------
// Refine + gather: exact fp32 re-score of top-8, copy the winner row.
// ---------------------------------------------------------------------------
__global__ void refine_gather_kernel(const float* __restrict__ x,
                                     const float* __restrict__ emb,
                                     float* __restrict__ out) {
    int row  = (blockIdx.x * blockDim.x + threadIdx.x) >> 5;
    int lane = threadIdx.x & 31;
    int cand[8];
#pragma unroll
    for (int c = 0; c < 8; ++c) cand[c] = g_top8[row][c];

    const float4* xr = reinterpret_cast<const float4*>(x + (size_t)row * DIM);
    float d[8] = {0.f, 0.f, 0.f, 0.f, 0.f, 0.f, 0.f, 0.f};
#pragma unroll
    for (int j = 0; j < 4; ++j) {
        float4 xv = xr[lane + j * 32];
#pragma unroll
        for (int c = 0; c < 8; ++c) {
            const float4* er = reinterpret_cast<const float4*>(
                emb + (size_t)cand[c] * DIM);
            float4 e = er[lane + j * 32];
            d[c] += xv.x * e.x + xv.y * e.y + xv.z * e.z + xv.w * e.w;
        }
    }
#pragma unroll
    for (int o = 16; o; o >>= 1)
#pragma unroll
        for (int c = 0; c < 8; ++c)
            d[c] += __shfl_xor_sync(0xffffffffu, d[c], o);

    float bs = d[0] - 0.5f * g_e2[cand[0]];
    int   bi = cand[0];
#pragma unroll
    for (int c = 1; c < 8; ++c) {
        float s = d[c] - 0.5f * g_e2[cand[c]];
        if (s > bs || (s == bs && cand[c] < bi)) { bs = s; bi = cand[c]; }
    }

    const float4* src = reinterpret_cast<const float4*>(emb + (size_t)bi * DIM);
    float4*       dst = reinterpret_cast<float4*>(out + (size_t)row * DIM);
#pragma unroll
    for (int j = 0; j < 4; ++j) dst[lane + j * 32] = src[lane + j * 32];
}

// ---------------------------------------------------------------------------
extern "C" void kernel_launch(void* const* d_in, const int* in_sizes, int n_in,
                              void* d_out, int out_size) {
    const float* x   = (const float*)d_in[0];
    const float* emb = (const float*)d_in[1];
    float*       out = (float*)d_out;

    cudaFuncSetAttribute(vq_main_kernel,
                         cudaFuncAttributeMaxDynamicSharedMemorySize, SMEM_TOTAL);

    e2_kernel<<<K_CODES / 8, 256>>>(emb);
    cvt_x_kernel<<<(M_TOTAL * DIM / 4) / 256, 256>>>(x);
    cvt_e_kernel<<<(K_CODES * DIM / 4) / 256, 256>>>(emb);
    vq_main_kernel<<<M_TOTAL / MT, NTHR, SMEM_TOTAL>>>();
    refine_gather_kernel<<<M_TOTAL / 8, 256>>>(x, emb, out);
}